// round 1
// baseline (speedup 1.0000x reference)
#include <cuda_runtime.h>
#include <cstdint>

#define NN     10000
#define EE     160000
#define ENTOT  (EE + NN)
#define TT     32
#define INC    128
#define HIDC   64
#define NHEADS 8
#define F1     512     // NHEADS * HIDC
#define GH     256
#define G3     768     // 3 * GH

// ---------------- scratch (device globals; no allocations allowed) ----------
__device__ float g_degf[NN];
__device__ float g_loopsum[NN * 3];
__device__ int   g_cnt[NN];
__device__ int   g_rowptr[NN + 1];
__device__ int   g_fill[NN];
__device__ int   g_adj_src[ENTOT];
__device__ float g_adj_ea[ENTOT * 3];
__device__ float g_xl1[NN * F1];
__device__ float g_xr1[NN * F1];
__device__ float g_h1 [NN * F1];
__device__ float g_xl2[NN * HIDC];
__device__ float g_xr2[NN * HIDC];
__device__ float g_emb[(size_t)TT * NN * HIDC];
__device__ float g_gi[NN * G3];
__device__ float g_gh[NN * G3];
__device__ float g_hf[NN * GH];
__device__ float g_hb[NN * GH];
__device__ float g_mean[2 * GH];

// ---------------- utility kernels ----------------
__global__ void k_zero_f(float* p, int n) {
    int i = blockIdx.x * blockDim.x + threadIdx.x;
    if (i < n) p[i] = 0.f;
}
__global__ void k_zero_i(int* p, int n) {
    int i = blockIdx.x * blockDim.x + threadIdx.x;
    if (i < n) p[i] = 0;
}

// ---------------- CSR precompute ----------------
__global__ void k_count(const float* __restrict__ ea, const int* __restrict__ dst,
                        float* degf, float* loopsum, int* cnt) {
    int e = blockIdx.x * blockDim.x + threadIdx.x;
    if (e >= EE) return;
    int d = dst[e];
    atomicAdd(&degf[d], 1.f);
    atomicAdd(&cnt[d], 1);
    atomicAdd(&loopsum[d * 3 + 0], ea[e * 3 + 0]);
    atomicAdd(&loopsum[d * 3 + 1], ea[e * 3 + 1]);
    atomicAdd(&loopsum[d * 3 + 2], ea[e * 3 + 2]);
}

// single-block inclusive scan of (cnt[i]+1) -> rowptr (exclusive form)
__global__ void k_scan(const int* __restrict__ cnt, int* __restrict__ rowptr) {
    __shared__ int tmp[1024];
    __shared__ int carry_s;
    int tid = threadIdx.x;
    if (tid == 0) { carry_s = 0; rowptr[0] = 0; }
    __syncthreads();
    for (int base = 0; base < NN; base += 1024) {
        int i = base + tid;
        int v = (i < NN) ? (cnt[i] + 1) : 0;   // +1 self loop
        tmp[tid] = v;
        __syncthreads();
        #pragma unroll
        for (int off = 1; off < 1024; off <<= 1) {
            int t = (tid >= off) ? tmp[tid - off] : 0;
            __syncthreads();
            tmp[tid] += t;
            __syncthreads();
        }
        if (i < NN) rowptr[i + 1] = carry_s + tmp[tid];
        __syncthreads();
        if (tid == 0) carry_s += tmp[1023];
        __syncthreads();
    }
}

__global__ void k_scatter_e(const float* __restrict__ ea, const int* __restrict__ src,
                            const int* __restrict__ dst, const int* __restrict__ rowptr,
                            int* fill, int* adj_src, float* adj_ea) {
    int e = blockIdx.x * blockDim.x + threadIdx.x;
    if (e >= EE) return;
    int d = dst[e];
    int pos = rowptr[d] + atomicAdd(&fill[d], 1);
    adj_src[pos] = src[e];
    adj_ea[pos * 3 + 0] = ea[e * 3 + 0];
    adj_ea[pos * 3 + 1] = ea[e * 3 + 1];
    adj_ea[pos * 3 + 2] = ea[e * 3 + 2];
}

__global__ void k_scatter_loop(const float* __restrict__ degf, const float* __restrict__ loopsum,
                               const int* __restrict__ rowptr, int* fill,
                               int* adj_src, float* adj_ea) {
    int n = blockIdx.x * blockDim.x + threadIdx.x;
    if (n >= NN) return;
    int pos = rowptr[n] + atomicAdd(&fill[n], 1);
    adj_src[pos] = n;
    float dm = fmaxf(degf[n], 1.f);
    adj_ea[pos * 3 + 0] = loopsum[n * 3 + 0] / dm;
    adj_ea[pos * 3 + 1] = loopsum[n * 3 + 1] / dm;
    adj_ea[pos * 3 + 2] = loopsum[n * 3 + 2] / dm;
}

// ---------------- generic fp32 tiled GEMM: C[M,N] = A[M,K] @ B ----------------
// BT=false : B is [K,N] row-major.  BT=true : B is [N,K] row-major (C = A @ B^T)
// Requires K % 16 == 0, N % 64 == 0. M ragged OK.
template <bool BT>
__global__ void gemm64(const float* __restrict__ A, const float* __restrict__ B,
                       float* __restrict__ C, int M, int N, int K) {
    __shared__ float As[16][68];
    __shared__ float Bs[16][68];
    int tid = threadIdx.x;
    int tx = tid & 15, ty = tid >> 4;
    int bm = blockIdx.y * 64, bn = blockIdx.x * 64;
    float acc[4][4];
    #pragma unroll
    for (int i = 0; i < 4; i++)
        #pragma unroll
        for (int j = 0; j < 4; j++) acc[i][j] = 0.f;

    for (int k0 = 0; k0 < K; k0 += 16) {
        #pragma unroll
        for (int i = 0; i < 4; i++) {
            int idx = tid + i * 256;
            int mm = idx >> 4, kk = idx & 15;
            int row = bm + mm;
            As[kk][mm] = (row < M) ? A[(size_t)row * K + k0 + kk] : 0.f;
        }
        if (!BT) {
            #pragma unroll
            for (int i = 0; i < 4; i++) {
                int idx = tid + i * 256;
                int nn = idx & 63, kk = idx >> 6;
                Bs[kk][nn] = B[(size_t)(k0 + kk) * N + bn + nn];
            }
        } else {
            #pragma unroll
            for (int i = 0; i < 4; i++) {
                int idx = tid + i * 256;
                int nn = idx >> 4, kk = idx & 15;
                Bs[kk][nn] = B[(size_t)(bn + nn) * K + k0 + kk];
            }
        }
        __syncthreads();
        #pragma unroll
        for (int kk = 0; kk < 16; kk++) {
            float a0 = As[kk][ty * 4 + 0], a1 = As[kk][ty * 4 + 1];
            float a2 = As[kk][ty * 4 + 2], a3 = As[kk][ty * 4 + 3];
            float b0 = Bs[kk][tx * 4 + 0], b1 = Bs[kk][tx * 4 + 1];
            float b2 = Bs[kk][tx * 4 + 2], b3 = Bs[kk][tx * 4 + 3];
            acc[0][0] += a0 * b0; acc[0][1] += a0 * b1; acc[0][2] += a0 * b2; acc[0][3] += a0 * b3;
            acc[1][0] += a1 * b0; acc[1][1] += a1 * b1; acc[1][2] += a1 * b2; acc[1][3] += a1 * b3;
            acc[2][0] += a2 * b0; acc[2][1] += a2 * b1; acc[2][2] += a2 * b2; acc[2][3] += a2 * b3;
            acc[3][0] += a3 * b0; acc[3][1] += a3 * b1; acc[3][2] += a3 * b2; acc[3][3] += a3 * b3;
        }
        __syncthreads();
    }
    #pragma unroll
    for (int i = 0; i < 4; i++) {
        int row = bm + ty * 4 + i;
        if (row < M) {
            #pragma unroll
            for (int j = 0; j < 4; j++)
                C[(size_t)row * N + bn + tx * 4 + j] = acc[i][j];
        }
    }
}

// ---------------- fused GATv2 edge kernel (one block per dst node) ----------
// block = NH*64 threads; thread tid = (h, c). Online softmax over incoming edges.
// out[n, tid] = ELU( sum_e alpha_e * xl[src_e, tid] + bias[tid] )
template <int NH>
__global__ void gat_edge(const float* __restrict__ xl, const float* __restrict__ xr,
                         const float* __restrict__ we,  const float* __restrict__ att,
                         const float* __restrict__ bias,
                         const int* __restrict__ rowptr, const int* __restrict__ adj_src,
                         const float* __restrict__ adj_ea,
                         float* __restrict__ out) {
    constexpr int F = NH * 64;
    __shared__ float s_xr[F];
    __shared__ float s_part[F / 32];
    int n = blockIdx.x;
    int tid = threadIdx.x;
    int h = tid >> 6;
    int warp = tid >> 5, lane = tid & 31;

    s_xr[tid] = xr[(size_t)n * F + tid];
    float attv = att[tid];
    float w0 = we[tid], w1 = we[F + tid], w2 = we[2 * F + tid];
    float bv = bias[tid];
    int beg = rowptr[n], end = rowptr[n + 1];
    float m_run = -1e30f, s_run = 0.f, acc = 0.f;
    __syncthreads();

    for (int p = beg; p < end; ++p) {
        int src = adj_src[p];
        float ea0 = adj_ea[3 * p + 0];
        float ea1 = adj_ea[3 * p + 1];
        float ea2 = adj_ea[3 * p + 2];
        float xlv = __ldg(&xl[(size_t)src * F + tid]);
        float m = xlv + s_xr[tid] + ea0 * w0 + ea1 * w1 + ea2 * w2;
        m = (m > 0.f) ? m : 0.2f * m;          // leaky relu
        float part = m * attv;
        #pragma unroll
        for (int off = 16; off; off >>= 1)
            part += __shfl_xor_sync(0xffffffffu, part, off);
        if (lane == 0) s_part[warp] = part;
        __syncthreads();
        float logit = s_part[2 * h] + s_part[2 * h + 1];
        float newm = fmaxf(m_run, logit);
        float sc = __expf(m_run - newm);
        float w  = __expf(logit - newm);
        s_run = s_run * sc + w;
        acc   = acc * sc + w * xlv;
        m_run = newm;
        __syncthreads();
    }
    float o = acc / s_run + bv;
    o = (o > 0.f) ? o : (__expf(o) - 1.f);     // ELU
    out[(size_t)n * F + tid] = o;
}

// ---------------- GRU gate kernel ----------------
__global__ void gru_gate(const float* __restrict__ gi, const float* __restrict__ gh,
                         const float* __restrict__ bih, const float* __restrict__ bhh,
                         float* __restrict__ h) {
    int idx = blockIdx.x * blockDim.x + threadIdx.x;
    if (idx >= NN * GH) return;
    int n = idx / GH, j = idx % GH;
    const float* gin = gi + (size_t)n * G3;
    const float* ghn = gh + (size_t)n * G3;
    float r = 1.f / (1.f + __expf(-(gin[j]        + bih[j]        + ghn[j]        + bhh[j])));
    float z = 1.f / (1.f + __expf(-(gin[GH + j]   + bih[GH + j]   + ghn[GH + j]   + bhh[GH + j])));
    float nv = tanhf(gin[2*GH + j] + bih[2*GH + j] + r * (ghn[2*GH + j] + bhh[2*GH + j]));
    float hv = h[idx];
    h[idx] = (1.f - z) * nv + z * hv;
}

// ---------------- final reductions ----------------
__global__ void k_colmean(const float* __restrict__ hf, const float* __restrict__ hb,
                          float* __restrict__ mean) {
    int j = blockIdx.x;  // 0..511
    const float* base = (j < GH) ? (hf + j) : (hb + (j - GH));
    float s = 0.f;
    for (int n = threadIdx.x; n < NN; n += blockDim.x) s += base[(size_t)n * GH];
    __shared__ float sh[256];
    sh[threadIdx.x] = s;
    __syncthreads();
    for (int o = 128; o; o >>= 1) {
        if (threadIdx.x < o) sh[threadIdx.x] += sh[threadIdx.x + o];
        __syncthreads();
    }
    if (threadIdx.x == 0) mean[j] = sh[0] * (1.f / (float)NN);
}

__global__ void k_fc(const float* __restrict__ w, const float* __restrict__ b,
                     const float* __restrict__ mean, float* __restrict__ out) {
    int i = blockIdx.x;  // 0..32
    float s = 0.f;
    for (int j = threadIdx.x; j < 2 * GH; j += blockDim.x) s += w[i * 2 * GH + j] * mean[j];
    __shared__ float sh[128];
    sh[threadIdx.x] = s;
    __syncthreads();
    for (int o = 64; o; o >>= 1) {
        if (threadIdx.x < o) sh[threadIdx.x] += sh[threadIdx.x + o];
        __syncthreads();
    }
    if (threadIdx.x == 0) out[i] = sh[0] + b[i];
}

// ---------------- host ----------------
static void gemm(const float* A, const float* B, float* C, int M, int N, int K, bool bt) {
    dim3 g(N / 64, (M + 63) / 64);
    if (bt) gemm64<true><<<g, 256>>>(A, B, C, M, N, K);
    else    gemm64<false><<<g, 256>>>(A, B, C, M, N, K);
}

extern "C" void kernel_launch(void* const* d_in, const int* in_sizes, int n_in,
                              void* d_out, int out_size) {
    const float* x        = (const float*)d_in[0];
    const float* edge_ea  = (const float*)d_in[1];
    const int*   edge_src = (const int*)  d_in[2];
    const int*   edge_dst = (const int*)  d_in[3];
    const float* gat1_wl  = (const float*)d_in[4];
    const float* gat1_wr  = (const float*)d_in[5];
    const float* gat1_we  = (const float*)d_in[6];
    const float* gat1_att = (const float*)d_in[7];
    const float* gat1_b   = (const float*)d_in[8];
    const float* gat2_wl  = (const float*)d_in[9];
    const float* gat2_wr  = (const float*)d_in[10];
    const float* gat2_we  = (const float*)d_in[11];
    const float* gat2_att = (const float*)d_in[12];
    const float* gat2_b   = (const float*)d_in[13];
    const float* wih_f    = (const float*)d_in[14];
    const float* whh_f    = (const float*)d_in[15];
    const float* bih_f    = (const float*)d_in[16];
    const float* bhh_f    = (const float*)d_in[17];
    const float* wih_b    = (const float*)d_in[18];
    const float* whh_b    = (const float*)d_in[19];
    const float* bih_b    = (const float*)d_in[20];
    const float* bhh_b    = (const float*)d_in[21];
    const float* fc_w     = (const float*)d_in[22];
    const float* fc_b     = (const float*)d_in[23];
    float* out = (float*)d_out;

    // resolve scratch symbols
    float *p_degf, *p_loopsum, *p_adj_ea, *p_xl1, *p_xr1, *p_h1, *p_xl2, *p_xr2;
    float *p_emb, *p_gi, *p_gh, *p_hf, *p_hb, *p_mean;
    int *p_cnt, *p_rowptr, *p_fill, *p_adj_src;
    cudaGetSymbolAddress((void**)&p_degf, g_degf);
    cudaGetSymbolAddress((void**)&p_loopsum, g_loopsum);
    cudaGetSymbolAddress((void**)&p_cnt, g_cnt);
    cudaGetSymbolAddress((void**)&p_rowptr, g_rowptr);
    cudaGetSymbolAddress((void**)&p_fill, g_fill);
    cudaGetSymbolAddress((void**)&p_adj_src, g_adj_src);
    cudaGetSymbolAddress((void**)&p_adj_ea, g_adj_ea);
    cudaGetSymbolAddress((void**)&p_xl1, g_xl1);
    cudaGetSymbolAddress((void**)&p_xr1, g_xr1);
    cudaGetSymbolAddress((void**)&p_h1,  g_h1);
    cudaGetSymbolAddress((void**)&p_xl2, g_xl2);
    cudaGetSymbolAddress((void**)&p_xr2, g_xr2);
    cudaGetSymbolAddress((void**)&p_emb, g_emb);
    cudaGetSymbolAddress((void**)&p_gi,  g_gi);
    cudaGetSymbolAddress((void**)&p_gh,  g_gh);
    cudaGetSymbolAddress((void**)&p_hf,  g_hf);
    cudaGetSymbolAddress((void**)&p_hb,  g_hb);
    cudaGetSymbolAddress((void**)&p_mean, g_mean);

    const int TB = 256;
    // ---- CSR precompute ----
    k_zero_f<<<(NN + TB - 1) / TB, TB>>>(p_degf, NN);
    k_zero_f<<<(3 * NN + TB - 1) / TB, TB>>>(p_loopsum, 3 * NN);
    k_zero_i<<<(NN + TB - 1) / TB, TB>>>(p_cnt, NN);
    k_count<<<(EE + TB - 1) / TB, TB>>>(edge_ea, edge_dst, p_degf, p_loopsum, p_cnt);
    k_scan<<<1, 1024>>>(p_cnt, p_rowptr);
    k_zero_i<<<(NN + TB - 1) / TB, TB>>>(p_fill, NN);
    k_scatter_e<<<(EE + TB - 1) / TB, TB>>>(edge_ea, edge_src, edge_dst, p_rowptr,
                                            p_fill, p_adj_src, p_adj_ea);
    k_scatter_loop<<<(NN + TB - 1) / TB, TB>>>(p_degf, p_loopsum, p_rowptr,
                                               p_fill, p_adj_src, p_adj_ea);

    // ---- per-timestep GAT stack ----
    for (int t = 0; t < TT; t++) {
        const float* xt = x + (size_t)t * NN * INC;
        gemm(xt, gat1_wl, p_xl1, NN, F1, INC, false);
        gemm(xt, gat1_wr, p_xr1, NN, F1, INC, false);
        gat_edge<NHEADS><<<NN, F1>>>(p_xl1, p_xr1, gat1_we, gat1_att, gat1_b,
                                     p_rowptr, p_adj_src, p_adj_ea, p_h1);
        gemm(p_h1, gat2_wl, p_xl2, NN, HIDC, F1, false);
        gemm(p_h1, gat2_wr, p_xr2, NN, HIDC, F1, false);
        gat_edge<1><<<NN, HIDC>>>(p_xl2, p_xr2, gat2_we, gat2_att, gat2_b,
                                  p_rowptr, p_adj_src, p_adj_ea,
                                  p_emb + (size_t)t * NN * HIDC);
    }

    // ---- GRU forward ----
    k_zero_f<<<(NN * GH + TB - 1) / TB, TB>>>(p_hf, NN * GH);
    for (int t = 0; t < TT; t++) {
        gemm(p_emb + (size_t)t * NN * HIDC, wih_f, p_gi, NN, G3, HIDC, true);
        gemm(p_hf, whh_f, p_gh, NN, G3, GH, true);
        gru_gate<<<(NN * GH + TB - 1) / TB, TB>>>(p_gi, p_gh, bih_f, bhh_f, p_hf);
    }
    // ---- GRU backward (reversed sequence) ----
    k_zero_f<<<(NN * GH + TB - 1) / TB, TB>>>(p_hb, NN * GH);
    for (int tt = 0; tt < TT; tt++) {
        int t = TT - 1 - tt;
        gemm(p_emb + (size_t)t * NN * HIDC, wih_b, p_gi, NN, G3, HIDC, true);
        gemm(p_hb, whh_b, p_gh, NN, G3, GH, true);
        gru_gate<<<(NN * GH + TB - 1) / TB, TB>>>(p_gi, p_gh, bih_b, bhh_b, p_hb);
    }

    // ---- mean + FC ----
    k_colmean<<<2 * GH, 256>>>(p_hf, p_hb, p_mean);
    k_fc<<<33, 128>>>(fc_w, fc_b, p_mean, out);
}

// round 4
// speedup vs baseline: 1.2381x; 1.2381x over previous
#include <cuda_runtime.h>
#include <cstdint>

#define NN     10000
#define EE     160000
#define ENTOT  (EE + NN)
#define TT     32
#define INC    128
#define HIDC   64
#define NHEADS 8
#define F1     512     // NHEADS * HID
#define GH     256
#define G3     768     // 3 * GH

// ---------------- scratch (device globals; no allocations allowed) ----------
__device__ float g_degf[NN];
__device__ float g_loopsum[NN * 3];
__device__ int   g_cnt[NN];
__device__ int   g_rowptr[NN + 1];
__device__ int   g_fill[NN];
__device__ int   g_adj_src[ENTOT];
__device__ float g_adj_ea[ENTOT * 3];
__device__ float g_xlr1[(size_t)NN * 2 * F1];    // [N, 1024] = xl1 | xr1
__device__ float g_h1 [NN * F1];
__device__ float g_xlr2[NN * 2 * HIDC];          // [N, 128] = xl2 | xr2
__device__ float g_emb[(size_t)TT * NN * HIDC];
__device__ float g_giT[(size_t)TT * NN * G3];    // batched input-gate activations
__device__ float g_gh[NN * G3];
__device__ float g_hf[NN * GH];
__device__ float g_hb[NN * GH];
__device__ float g_mean[2 * GH];
// transposed/concatenated weights [Nout, K]
__device__ float g_w1cat[2 * F1 * INC];          // [1024, 128]
__device__ float g_w2cat[2 * HIDC * F1];         // [128, 512]

// ---------------- swizzle ----------------
#define SWZ(off) ((off) ^ (((off) >> 3) & 0x70))

__device__ __forceinline__ uint32_t smem_u32(const void* p) {
    uint32_t a;
    asm("{ .reg .u64 t; cvta.to.shared.u64 t, %1; cvt.u32.u64 %0, t; }" : "=r"(a) : "l"(p));
    return a;
}
__device__ __forceinline__ void cp_async16(uint32_t dst, const void* src, int sz) {
    asm volatile("cp.async.ca.shared.global [%0], [%1], 16, %2;"
                 :: "r"(dst), "l"(src), "r"(sz) : "memory");
}
__device__ __forceinline__ void cp_commit() {
    asm volatile("cp.async.commit_group;" ::: "memory");
}
__device__ __forceinline__ void cp_wait1() {
    asm volatile("cp.async.wait_group 1;" ::: "memory");
}
__device__ __forceinline__ void cp_wait0() {
    asm volatile("cp.async.wait_group 0;" ::: "memory");
}
__device__ __forceinline__ void ldsm_x4(uint32_t& r0, uint32_t& r1, uint32_t& r2, uint32_t& r3,
                                        uint32_t addr) {
    asm volatile("ldmatrix.sync.aligned.m8n8.x4.shared.b16 {%0,%1,%2,%3}, [%4];"
                 : "=r"(r0), "=r"(r1), "=r"(r2), "=r"(r3) : "r"(addr));
}
__device__ __forceinline__ void mma_tf32(float* c, uint32_t a0, uint32_t a1, uint32_t a2,
                                         uint32_t a3, uint32_t b0, uint32_t b1) {
    asm volatile("mma.sync.aligned.m16n8k8.row.col.f32.tf32.tf32.f32 "
                 "{%0,%1,%2,%3}, {%4,%5,%6,%7}, {%8,%9}, {%0,%1,%2,%3};"
                 : "+f"(c[0]), "+f"(c[1]), "+f"(c[2]), "+f"(c[3])
                 : "r"(a0), "r"(a1), "r"(a2), "r"(a3), "r"(b0), "r"(b1));
}
// split fp32 into tf32 hi + tf32 lo (3xTF32 emulation)
__device__ __forceinline__ void split_tf32(uint32_t raw, uint32_t& hi, uint32_t& lo) {
    float f = __uint_as_float(raw);
    asm("cvt.rna.tf32.f32 %0, %1;" : "=r"(hi) : "f"(f));
    float r = f - __uint_as_float(hi);
    asm("cvt.rna.tf32.f32 %0, %1;" : "=r"(lo) : "f"(r));
}

// ---------------- 3xTF32 mma.sync GEMM: C[M,N] = A[M,K] @ BT[N,K]^T ----------
// BM=128, BN=128, BK=32. 256 threads = 8 warps (2 along M x 4 along N).
// Warp tile 64x32. Requires K%32==0, N%128==0. M ragged OK.
// Emulated fp32 precision: per atom pair, acc += Ahi*Bhi + Ahi*Blo + Alo*Bhi.
__global__ void __launch_bounds__(256) tgemm(
    const float* __restrict__ A, const float* __restrict__ BT,
    float* __restrict__ C, int M, int N, int K)
{
    constexpr int ASZ = 128 * 128;        // bytes per A stage (128 rows x 32 fl)
    constexpr int STAGE = 2 * ASZ;        // A + B per stage
    extern __shared__ char smem[];
    const uint32_t sbase = smem_u32(smem);
    const int t = threadIdx.x;
    const int warp = t >> 5, lane = t & 31;
    const int wm0 = (warp & 1) * 64;      // warp M offset
    const int wn0 = (warp >> 1) * 32;     // warp N offset
    const int bm = blockIdx.y * 128;
    const int bn = blockIdx.x * 128;

    float acc[4][4][4];                    // [m-atom][n-atom][4]
    #pragma unroll
    for (int i = 0; i < 4; i++)
        #pragma unroll
        for (int j = 0; j < 4; j++)
            #pragma unroll
            for (int k = 0; k < 4; k++) acc[i][j][k] = 0.f;

    const int NC = K >> 5;

    auto load_stage = [&](int s, int k0) {
        uint32_t sa = sbase + s * STAGE;
        uint32_t sb = sa + ASZ;
        #pragma unroll
        for (int i = 0; i < 4; i++) {
            int idx = t + i * 256;
            int row = idx >> 3, c4 = idx & 7;
            const float* src = A + (size_t)(bm + row) * K + k0 + c4 * 4;
            int sz = (bm + row < M) ? 16 : 0;
            cp_async16(sa + SWZ((row << 7) | (c4 << 4)), src, sz);
        }
        #pragma unroll
        for (int i = 0; i < 4; i++) {
            int idx = t + i * 256;
            int row = idx >> 3, c4 = idx & 7;
            const float* src = BT + (size_t)(bn + row) * K + k0 + c4 * 4;
            cp_async16(sb + SWZ((row << 7) | (c4 << 4)), src, 16);
        }
        cp_commit();
    };

    load_stage(0, 0);

    for (int c = 0; c < NC; c++) {
        if (c + 1 < NC) { load_stage((c + 1) & 1, (c + 1) << 5); cp_wait1(); }
        else            { cp_wait0(); }
        __syncthreads();

        uint32_t sa = sbase + (c & 1) * STAGE;
        uint32_t sb = sa + ASZ;
        #pragma unroll
        for (int ks = 0; ks < 4; ks++) {
            int kb = ks << 5;
            uint32_t ah[4][4], al[4][4], bh[2][4], bl[2][4];
            // A fragments: 4 m-atoms of 16 rows
            #pragma unroll
            for (int ma = 0; ma < 4; ma++) {
                int tI = lane >> 3, r = lane & 7;
                int row = wm0 + ma * 16 + ((tI & 1) << 3) + r;
                int kk = kb + ((tI & 2) << 3);
                uint32_t r0, r1, r2, r3;
                ldsm_x4(r0, r1, r2, r3, sa + SWZ((row << 7) | kk));
                split_tf32(r0, ah[ma][0], al[ma][0]);
                split_tf32(r1, ah[ma][1], al[ma][1]);
                split_tf32(r2, ah[ma][2], al[ma][2]);
                split_tf32(r3, ah[ma][3], al[ma][3]);
            }
            // B fragments: 2 x (2 n-atoms)
            #pragma unroll
            for (int nb = 0; nb < 2; nb++) {
                int r = lane & 7;
                int half = (lane >> 4) & 1;
                int khalf = (lane >> 3) & 1;
                int row = wn0 + nb * 16 + (half << 3) + r;
                int kk = kb + (khalf << 4);
                uint32_t r0, r1, r2, r3;
                ldsm_x4(r0, r1, r2, r3, sb + SWZ((row << 7) | kk));
                split_tf32(r0, bh[nb][0], bl[nb][0]);
                split_tf32(r1, bh[nb][1], bl[nb][1]);
                split_tf32(r2, bh[nb][2], bl[nb][2]);
                split_tf32(r3, bh[nb][3], bl[nb][3]);
            }
            #pragma unroll
            for (int ma = 0; ma < 4; ma++)
                #pragma unroll
                for (int na = 0; na < 4; na++) {
                    int nb = na >> 1, nh = (na & 1) * 2;
                    // hi*lo + lo*hi first, hi*hi last (large term last helps rounding)
                    mma_tf32(acc[ma][na], ah[ma][0], ah[ma][1], ah[ma][2], ah[ma][3],
                             bl[nb][nh], bl[nb][nh + 1]);
                    mma_tf32(acc[ma][na], al[ma][0], al[ma][1], al[ma][2], al[ma][3],
                             bh[nb][nh], bh[nb][nh + 1]);
                    mma_tf32(acc[ma][na], ah[ma][0], ah[ma][1], ah[ma][2], ah[ma][3],
                             bh[nb][nh], bh[nb][nh + 1]);
                }
        }
        __syncthreads();
    }

    // epilogue
    #pragma unroll
    for (int ma = 0; ma < 4; ma++) {
        int row = bm + wm0 + ma * 16 + (lane >> 2);
        #pragma unroll
        for (int na = 0; na < 4; na++) {
            int col = bn + wn0 + na * 8 + 2 * (lane & 3);
            if (row < M)
                *reinterpret_cast<float2*>(&C[(size_t)row * N + col]) =
                    make_float2(acc[ma][na][0], acc[ma][na][1]);
            if (row + 8 < M)
                *reinterpret_cast<float2*>(&C[(size_t)(row + 8) * N + col]) =
                    make_float2(acc[ma][na][2], acc[ma][na][3]);
        }
    }
}

// ---------------- weight transpose: out[c*R + r] = in[r*C + c] -------------
__global__ void k_transpose(const float* __restrict__ in, float* __restrict__ out,
                            int R, int Ccols) {
    __shared__ float tile[32][33];
    int c0 = blockIdx.x * 32, r0 = blockIdx.y * 32;
    int x = threadIdx.x, y = threadIdx.y;
    for (int j = 0; j < 32; j += 8) {
        int r = r0 + y + j, c = c0 + x;
        if (r < R && c < Ccols) tile[y + j][x] = in[(size_t)r * Ccols + c];
    }
    __syncthreads();
    for (int j = 0; j < 32; j += 8) {
        int c = c0 + y + j, r = r0 + x;
        if (c < Ccols && r < R) out[(size_t)c * R + r] = tile[x][y + j];
    }
}

// ---------------- utility kernels ----------------
__global__ void k_zero_f(float* p, int n) {
    int i = blockIdx.x * blockDim.x + threadIdx.x;
    if (i < n) p[i] = 0.f;
}
__global__ void k_zero_i(int* p, int n) {
    int i = blockIdx.x * blockDim.x + threadIdx.x;
    if (i < n) p[i] = 0;
}

// ---------------- CSR precompute ----------------
__global__ void k_count(const float* __restrict__ ea, const int* __restrict__ dst,
                        float* degf, float* loopsum, int* cnt) {
    int e = blockIdx.x * blockDim.x + threadIdx.x;
    if (e >= EE) return;
    int d = dst[e];
    atomicAdd(&degf[d], 1.f);
    atomicAdd(&cnt[d], 1);
    atomicAdd(&loopsum[d * 3 + 0], ea[e * 3 + 0]);
    atomicAdd(&loopsum[d * 3 + 1], ea[e * 3 + 1]);
    atomicAdd(&loopsum[d * 3 + 2], ea[e * 3 + 2]);
}

__global__ void k_scan(const int* __restrict__ cnt, int* __restrict__ rowptr) {
    __shared__ int tmp[1024];
    __shared__ int carry_s;
    int tid = threadIdx.x;
    if (tid == 0) { carry_s = 0; rowptr[0] = 0; }
    __syncthreads();
    for (int base = 0; base < NN; base += 1024) {
        int i = base + tid;
        int v = (i < NN) ? (cnt[i] + 1) : 0;
        tmp[tid] = v;
        __syncthreads();
        #pragma unroll
        for (int off = 1; off < 1024; off <<= 1) {
            int tv = (tid >= off) ? tmp[tid - off] : 0;
            __syncthreads();
            tmp[tid] += tv;
            __syncthreads();
        }
        if (i < NN) rowptr[i + 1] = carry_s + tmp[tid];
        __syncthreads();
        if (tid == 0) carry_s += tmp[1023];
        __syncthreads();
    }
}

__global__ void k_scatter_e(const float* __restrict__ ea, const int* __restrict__ src,
                            const int* __restrict__ dst, const int* __restrict__ rowptr,
                            int* fill, int* adj_src, float* adj_ea) {
    int e = blockIdx.x * blockDim.x + threadIdx.x;
    if (e >= EE) return;
    int d = dst[e];
    int pos = rowptr[d] + atomicAdd(&fill[d], 1);
    adj_src[pos] = src[e];
    adj_ea[pos * 3 + 0] = ea[e * 3 + 0];
    adj_ea[pos * 3 + 1] = ea[e * 3 + 1];
    adj_ea[pos * 3 + 2] = ea[e * 3 + 2];
}

__global__ void k_scatter_loop(const float* __restrict__ degf, const float* __restrict__ loopsum,
                               const int* __restrict__ rowptr, int* fill,
                               int* adj_src, float* adj_ea) {
    int n = blockIdx.x * blockDim.x + threadIdx.x;
    if (n >= NN) return;
    int pos = rowptr[n] + atomicAdd(&fill[n], 1);
    adj_src[pos] = n;
    float dm = fmaxf(degf[n], 1.f);
    adj_ea[pos * 3 + 0] = loopsum[n * 3 + 0] / dm;
    adj_ea[pos * 3 + 1] = loopsum[n * 3 + 1] / dm;
    adj_ea[pos * 3 + 2] = loopsum[n * 3 + 2] / dm;
}

// ---------------- fused GATv2 edge kernel (one block per dst node) ----------
// xl/xr live in a combined [N, ldx] tensor (xr = xl + F column offset).
template <int NH>
__global__ void gat_edge(const float* __restrict__ xl, const float* __restrict__ xr,
                         int ldx,
                         const float* __restrict__ we,  const float* __restrict__ att,
                         const float* __restrict__ bias,
                         const int* __restrict__ rowptr, const int* __restrict__ adj_src,
                         const float* __restrict__ adj_ea,
                         float* __restrict__ out) {
    constexpr int F = NH * 64;
    __shared__ float s_xr[F];
    __shared__ float s_part[F / 32];
    int n = blockIdx.x;
    int tid = threadIdx.x;
    int h = tid >> 6;
    int warp = tid >> 5, lane = tid & 31;

    s_xr[tid] = xr[(size_t)n * ldx + tid];
    float attv = att[tid];
    float w0 = we[tid], w1 = we[F + tid], w2 = we[2 * F + tid];
    float bv = bias[tid];
    int beg = rowptr[n], end = rowptr[n + 1];
    float m_run = -1e30f, s_run = 0.f, acc = 0.f;
    __syncthreads();

    for (int p = beg; p < end; ++p) {
        int src = adj_src[p];
        float ea0 = adj_ea[3 * p + 0];
        float ea1 = adj_ea[3 * p + 1];
        float ea2 = adj_ea[3 * p + 2];
        float xlv = __ldg(&xl[(size_t)src * ldx + tid]);
        float m = xlv + s_xr[tid] + ea0 * w0 + ea1 * w1 + ea2 * w2;
        m = (m > 0.f) ? m : 0.2f * m;
        float part = m * attv;
        #pragma unroll
        for (int off = 16; off; off >>= 1)
            part += __shfl_xor_sync(0xffffffffu, part, off);
        if (lane == 0) s_part[warp] = part;
        __syncthreads();
        float logit = s_part[2 * h] + s_part[2 * h + 1];
        float newm = fmaxf(m_run, logit);
        float sc = __expf(m_run - newm);
        float w  = __expf(logit - newm);
        s_run = s_run * sc + w;
        acc   = acc * sc + w * xlv;
        m_run = newm;
        __syncthreads();
    }
    float o = acc / s_run + bv;
    o = (o > 0.f) ? o : (__expf(o) - 1.f);
    out[(size_t)n * F + tid] = o;
}

// ---------------- GRU gate kernel ----------------
__global__ void gru_gate(const float* __restrict__ gi, const float* __restrict__ gh,
                         const float* __restrict__ bih, const float* __restrict__ bhh,
                         float* __restrict__ h) {
    int idx = blockIdx.x * blockDim.x + threadIdx.x;
    if (idx >= NN * GH) return;
    int n = idx / GH, j = idx % GH;
    const float* gin = gi + (size_t)n * G3;
    const float* ghn = gh + (size_t)n * G3;
    float r = 1.f / (1.f + __expf(-(gin[j]      + bih[j]      + ghn[j]      + bhh[j])));
    float z = 1.f / (1.f + __expf(-(gin[GH + j] + bih[GH + j] + ghn[GH + j] + bhh[GH + j])));
    float nv = tanhf(gin[2 * GH + j] + bih[2 * GH + j] + r * (ghn[2 * GH + j] + bhh[2 * GH + j]));
    float hv = h[idx];
    h[idx] = (1.f - z) * nv + z * hv;
}

// ---------------- final reductions ----------------
__global__ void k_colmean(const float* __restrict__ hf, const float* __restrict__ hb,
                          float* __restrict__ mean) {
    int j = blockIdx.x;
    const float* base = (j < GH) ? (hf + j) : (hb + (j - GH));
    float s = 0.f;
    for (int n = threadIdx.x; n < NN; n += blockDim.x) s += base[(size_t)n * GH];
    __shared__ float sh[256];
    sh[threadIdx.x] = s;
    __syncthreads();
    for (int o = 128; o; o >>= 1) {
        if (threadIdx.x < o) sh[threadIdx.x] += sh[threadIdx.x + o];
        __syncthreads();
    }
    if (threadIdx.x == 0) mean[j] = sh[0] * (1.f / (float)NN);
}

__global__ void k_fc(const float* __restrict__ w, const float* __restrict__ b,
                     const float* __restrict__ mean, float* __restrict__ out) {
    int i = blockIdx.x;
    float s = 0.f;
    for (int j = threadIdx.x; j < 2 * GH; j += blockDim.x) s += w[i * 2 * GH + j] * mean[j];
    __shared__ float sh[128];
    sh[threadIdx.x] = s;
    __syncthreads();
    for (int o = 64; o; o >>= 1) {
        if (threadIdx.x < o) sh[threadIdx.x] += sh[threadIdx.x + o];
        __syncthreads();
    }
    if (threadIdx.x == 0) out[i] = sh[0] + b[i];
}

// ---------------- host ----------------
static const int GEMM_SMEM = 2 * 2 * 128 * 128;   // 65536

static void tg(const float* A, const float* BT, float* C, int M, int N, int K) {
    dim3 g(N / 128, (M + 127) / 128);
    tgemm<<<g, 256, GEMM_SMEM>>>(A, BT, C, M, N, K);
}

extern "C" void kernel_launch(void* const* d_in, const int* in_sizes, int n_in,
                              void* d_out, int out_size) {
    const float* x        = (const float*)d_in[0];
    const float* edge_ea  = (const float*)d_in[1];
    const int*   edge_src = (const int*)  d_in[2];
    const int*   edge_dst = (const int*)  d_in[3];
    const float* gat1_wl  = (const float*)d_in[4];
    const float* gat1_wr  = (const float*)d_in[5];
    const float* gat1_we  = (const float*)d_in[6];
    const float* gat1_att = (const float*)d_in[7];
    const float* gat1_b   = (const float*)d_in[8];
    const float* gat2_wl  = (const float*)d_in[9];
    const float* gat2_wr  = (const float*)d_in[10];
    const float* gat2_we  = (const float*)d_in[11];
    const float* gat2_att = (const float*)d_in[12];
    const float* gat2_b   = (const float*)d_in[13];
    const float* wih_f    = (const float*)d_in[14];
    const float* whh_f    = (const float*)d_in[15];
    const float* bih_f    = (const float*)d_in[16];
    const float* bhh_f    = (const float*)d_in[17];
    const float* wih_b    = (const float*)d_in[18];
    const float* whh_b    = (const float*)d_in[19];
    const float* bih_b    = (const float*)d_in[20];
    const float* bhh_b    = (const float*)d_in[21];
    const float* fc_w     = (const float*)d_in[22];
    const float* fc_b     = (const float*)d_in[23];
    float* out = (float*)d_out;

    cudaFuncSetAttribute(tgemm, cudaFuncAttributeMaxDynamicSharedMemorySize, GEMM_SMEM);

    float *p_degf, *p_loopsum, *p_adj_ea, *p_xlr1, *p_h1, *p_xlr2;
    float *p_emb, *p_giT, *p_gh, *p_hf, *p_hb, *p_mean;
    float *p_w1cat, *p_w2cat;
    int *p_cnt, *p_rowptr, *p_fill, *p_adj_src;
    cudaGetSymbolAddress((void**)&p_degf, g_degf);
    cudaGetSymbolAddress((void**)&p_loopsum, g_loopsum);
    cudaGetSymbolAddress((void**)&p_cnt, g_cnt);
    cudaGetSymbolAddress((void**)&p_rowptr, g_rowptr);
    cudaGetSymbolAddress((void**)&p_fill, g_fill);
    cudaGetSymbolAddress((void**)&p_adj_src, g_adj_src);
    cudaGetSymbolAddress((void**)&p_adj_ea, g_adj_ea);
    cudaGetSymbolAddress((void**)&p_xlr1, g_xlr1);
    cudaGetSymbolAddress((void**)&p_h1,  g_h1);
    cudaGetSymbolAddress((void**)&p_xlr2, g_xlr2);
    cudaGetSymbolAddress((void**)&p_emb, g_emb);
    cudaGetSymbolAddress((void**)&p_giT, g_giT);
    cudaGetSymbolAddress((void**)&p_gh,  g_gh);
    cudaGetSymbolAddress((void**)&p_hf,  g_hf);
    cudaGetSymbolAddress((void**)&p_hb,  g_hb);
    cudaGetSymbolAddress((void**)&p_mean, g_mean);
    cudaGetSymbolAddress((void**)&p_w1cat, g_w1cat);
    cudaGetSymbolAddress((void**)&p_w2cat, g_w2cat);

    const int TB = 256;
    // ---- CSR precompute ----
    k_zero_f<<<(NN + TB - 1) / TB, TB>>>(p_degf, NN);
    k_zero_f<<<(3 * NN + TB - 1) / TB, TB>>>(p_loopsum, 3 * NN);
    k_zero_i<<<(NN + TB - 1) / TB, TB>>>(p_cnt, NN);
    k_count<<<(EE + TB - 1) / TB, TB>>>(edge_ea, edge_dst, p_degf, p_loopsum, p_cnt);
    k_scan<<<1, 1024>>>(p_cnt, p_rowptr);
    k_zero_i<<<(NN + TB - 1) / TB, TB>>>(p_fill, NN);
    k_scatter_e<<<(EE + TB - 1) / TB, TB>>>(edge_ea, edge_src, edge_dst, p_rowptr,
                                            p_fill, p_adj_src, p_adj_ea);
    k_scatter_loop<<<(NN + TB - 1) / TB, TB>>>(p_degf, p_loopsum, p_rowptr,
                                               p_fill, p_adj_src, p_adj_ea);

    // ---- weight transposes into concatenated [Nout, K] ----
    {
        dim3 b(32, 8);
        // W1cat: rows 0..511 = wl^T, rows 512..1023 = wr^T  (K = 128)
        k_transpose<<<dim3(F1 / 32, INC / 32), b>>>(gat1_wl, p_w1cat, INC, F1);
        k_transpose<<<dim3(F1 / 32, INC / 32), b>>>(gat1_wr, p_w1cat + (size_t)F1 * INC, INC, F1);
        // W2cat: rows 0..63 = wl^T, rows 64..127 = wr^T  (K = 512)
        k_transpose<<<dim3(HIDC / 32, F1 / 32), b>>>(gat2_wl, p_w2cat, F1, HIDC);
        k_transpose<<<dim3(HIDC / 32, F1 / 32), b>>>(gat2_wr, p_w2cat + (size_t)HIDC * F1, F1, HIDC);
    }

    // ---- per-timestep GAT stack ----
    for (int t = 0; t < TT; t++) {
        const float* xt = x + (size_t)t * NN * INC;
        tg(xt, p_w1cat, p_xlr1, NN, 2 * F1, INC);               // [N,1024] = xl|xr
        gat_edge<NHEADS><<<NN, F1>>>(p_xlr1, p_xlr1 + F1, 2 * F1,
                                     gat1_we, gat1_att, gat1_b,
                                     p_rowptr, p_adj_src, p_adj_ea, p_h1);
        tg(p_h1, p_w2cat, p_xlr2, NN, 2 * HIDC, F1);            // [N,128] = xl|xr
        gat_edge<1><<<NN, HIDC>>>(p_xlr2, p_xlr2 + HIDC, 2 * HIDC,
                                  gat2_we, gat2_att, gat2_b,
                                  p_rowptr, p_adj_src, p_adj_ea,
                                  p_emb + (size_t)t * NN * HIDC);
    }

    // ---- GRU forward ----
    tg(p_emb, wih_f, p_giT, TT * NN, G3, HIDC);                 // batched gi, all T
    k_zero_f<<<(NN * GH + TB - 1) / TB, TB>>>(p_hf, NN * GH);
    for (int t = 0; t < TT; t++) {
        tg(p_hf, whh_f, p_gh, NN, G3, GH);
        gru_gate<<<(NN * GH + TB - 1) / TB, TB>>>(p_giT + (size_t)t * NN * G3,
                                                  p_gh, bih_f, bhh_f, p_hf);
    }
    // ---- GRU backward ----
    tg(p_emb, wih_b, p_giT, TT * NN, G3, HIDC);
    k_zero_f<<<(NN * GH + TB - 1) / TB, TB>>>(p_hb, NN * GH);
    for (int tt = 0; tt < TT; tt++) {
        int t = TT - 1 - tt;
        tg(p_hb, whh_b, p_gh, NN, G3, GH);
        gru_gate<<<(NN * GH + TB - 1) / TB, TB>>>(p_giT + (size_t)t * NN * G3,
                                                  p_gh, bih_b, bhh_b, p_hb);
    }

    // ---- mean + FC ----
    k_colmean<<<2 * GH, 256>>>(p_hf, p_hb, p_mean);
    k_fc<<<33, 128>>>(fc_w, fc_b, p_mean, out);
}

// round 5
// speedup vs baseline: 1.5611x; 1.2609x over previous
#include <cuda_runtime.h>
#include <cuda_bf16.h>
#include <cstdint>

#define NN     10000
#define EE     160000
#define ENTOT  (EE + NN)
#define TT     32
#define INC    128
#define HIDC   64
#define NHEADS 8
#define F1     512     // NHEADS * HID
#define GH     256
#define G3     768     // 3 * GH

// ---------------- scratch (device globals; no allocations allowed) ----------
__device__ float g_degf[NN];
__device__ float g_loopsum[NN * 3];
__device__ int   g_cnt[NN];
__device__ int   g_rowptr[NN + 1];
__device__ int   g_fill[NN];
__device__ int   g_adj_src[ENTOT];
__device__ float g_adj_ea[ENTOT * 3];
__device__ float g_xlr1[(size_t)NN * 2 * F1];    // [N, 1024] = xl1 | xr1  (fp32)
__device__ float g_xlr2[NN * 2 * HIDC];          // [N, 128]  = xl2 | xr2  (fp32)
__device__ float g_giT[(size_t)TT * NN * G3];    // batched input-gate activations
__device__ float g_gh[NN * G3];
__device__ float g_hf[NN * GH];
__device__ float g_hb[NN * GH];
__device__ float g_mean[2 * GH];

// bf16 hi/lo plane buffers: layout [hi(0..n) | lo(n..2n)]
__device__ __nv_bfloat16 g_xs  [(size_t)2 * TT * NN * INC];
__device__ __nv_bfloat16 g_w1s [2 * 2 * F1 * INC];
__device__ __nv_bfloat16 g_w2s [2 * 2 * HIDC * F1];
__device__ __nv_bfloat16 g_h1s [(size_t)2 * NN * F1];
__device__ __nv_bfloat16 g_embs[(size_t)2 * TT * NN * HIDC];
__device__ __nv_bfloat16 g_hfs [2 * NN * GH];
__device__ __nv_bfloat16 g_hbs [2 * NN * GH];
__device__ __nv_bfloat16 g_wihs_f[2 * G3 * HIDC];
__device__ __nv_bfloat16 g_wihs_b[2 * G3 * HIDC];
__device__ __nv_bfloat16 g_whhs_f[2 * G3 * GH];
__device__ __nv_bfloat16 g_whhs_b[2 * G3 * GH];

// ---------------- helpers ----------------
#define SWZ(off) ((off) ^ (((off) >> 3) & 0x70))

__device__ __forceinline__ uint32_t smem_u32(const void* p) {
    uint32_t a;
    asm("{ .reg .u64 t; cvta.to.shared.u64 t, %1; cvt.u32.u64 %0, t; }" : "=r"(a) : "l"(p));
    return a;
}
__device__ __forceinline__ void cp_async16(uint32_t dst, const void* src, int sz) {
    asm volatile("cp.async.ca.shared.global [%0], [%1], 16, %2;"
                 :: "r"(dst), "l"(src), "r"(sz) : "memory");
}
__device__ __forceinline__ void cp_commit() {
    asm volatile("cp.async.commit_group;" ::: "memory");
}
__device__ __forceinline__ void cp_wait1() {
    asm volatile("cp.async.wait_group 1;" ::: "memory");
}
__device__ __forceinline__ void cp_wait0() {
    asm volatile("cp.async.wait_group 0;" ::: "memory");
}
__device__ __forceinline__ void ldsm_x4(uint32_t* r, uint32_t addr) {
    asm volatile("ldmatrix.sync.aligned.m8n8.x4.shared.b16 {%0,%1,%2,%3}, [%4];"
                 : "=r"(r[0]), "=r"(r[1]), "=r"(r[2]), "=r"(r[3]) : "r"(addr));
}
__device__ __forceinline__ void mma_bf16(float* c, const uint32_t* a, uint32_t b0, uint32_t b1) {
    asm volatile("mma.sync.aligned.m16n8k16.row.col.f32.bf16.bf16.f32 "
                 "{%0,%1,%2,%3}, {%4,%5,%6,%7}, {%8,%9}, {%0,%1,%2,%3};"
                 : "+f"(c[0]), "+f"(c[1]), "+f"(c[2]), "+f"(c[3])
                 : "r"(a[0]), "r"(a[1]), "r"(a[2]), "r"(a[3]), "r"(b0), "r"(b1));
}
__device__ __forceinline__ void split_bf16(float v, __nv_bfloat16& hi, __nv_bfloat16& lo) {
    hi = __float2bfloat16_rn(v);
    lo = __float2bfloat16_rn(v - __bfloat162float(hi));
}

// ---- bf16x3 emulated-fp32 GEMM: C[M,N] = A[M,K] @ BT[N,K]^T -----------------
// A, B given as pre-split bf16 hi/lo planes ([M,K] bf16 each).
// BM=128, BN=128, BK=32 (fp32-k). smem row (128B) = [hi 64B | lo 64B], SW128.
// 256 threads = 8 warps (2 M x 4 N), warp tile 64x32. K%32==0, N%128==0.
__global__ void __launch_bounds__(256) tgemm(
    const __nv_bfloat16* __restrict__ Ahi, const __nv_bfloat16* __restrict__ Alo,
    const __nv_bfloat16* __restrict__ Bhi, const __nv_bfloat16* __restrict__ Blo,
    float* __restrict__ C, int M, int N, int K)
{
    constexpr int TSZ   = 128 * 128;      // bytes per tile (128 rows x 128B)
    constexpr int STAGE = 2 * TSZ;        // A + B per stage
    extern __shared__ char smem[];
    const uint32_t sbase = smem_u32(smem);
    const int t = threadIdx.x;
    const int warp = t >> 5, lane = t & 31;
    const int tI = lane >> 3, lr = lane & 7;
    const int wm0 = (warp & 1) * 64;
    const int wn0 = (warp >> 1) * 32;
    const int bm = blockIdx.y * 128;
    const int bn = blockIdx.x * 128;
    const size_t Kb = (size_t)K * 2;      // bytes per plane row

    float acc[4][4][4];
    #pragma unroll
    for (int i = 0; i < 4; i++)
        #pragma unroll
        for (int j = 0; j < 4; j++)
            #pragma unroll
            for (int k = 0; k < 4; k++) acc[i][j][k] = 0.f;

    const int NC = K >> 5;

    auto load_stage = [&](int s, int c) {
        uint32_t sa = sbase + s * STAGE;
        uint32_t sb = sa + TSZ;
        int k0b = c << 6;                 // 32 fp32-k = 64 bytes bf16
        #pragma unroll
        for (int i = 0; i < 4; i++) {
            int idx = t + i * 256;
            int row = idx >> 3, c8 = idx & 7;
            const char* base = (const char*)((c8 & 4) ? Alo : Ahi);
            const char* src = base + (size_t)(bm + row) * Kb + k0b + (c8 & 3) * 16;
            int sz = (bm + row < M) ? 16 : 0;
            cp_async16(sa + SWZ((row << 7) | (c8 << 4)), src, sz);
        }
        #pragma unroll
        for (int i = 0; i < 4; i++) {
            int idx = t + i * 256;
            int row = idx >> 3, c8 = idx & 7;
            const char* base = (const char*)((c8 & 4) ? Blo : Bhi);
            const char* src = base + (size_t)(bn + row) * Kb + k0b + (c8 & 3) * 16;
            cp_async16(sb + SWZ((row << 7) | (c8 << 4)), src, 16);
        }
        cp_commit();
    };

    load_stage(0, 0);

    for (int c = 0; c < NC; c++) {
        if (c + 1 < NC) { load_stage((c + 1) & 1, c + 1); cp_wait1(); }
        else            { cp_wait0(); }
        __syncthreads();

        uint32_t sa = sbase + (c & 1) * STAGE;
        uint32_t sb = sa + TSZ;
        #pragma unroll
        for (int ks = 0; ks < 2; ks++) {      // two k16 slices per 32-k chunk
            uint32_t Ah[4][4], Al[4][4], Bh[2][4], Bl[2][4];
            #pragma unroll
            for (int ma = 0; ma < 4; ma++) {
                int row = wm0 + ma * 16 + ((tI & 1) << 3) + lr;
                int kb = (ks << 5) | ((tI >> 1) << 4);
                ldsm_x4(Ah[ma], sa + SWZ((row << 7) | kb));
                ldsm_x4(Al[ma], sa + SWZ((row << 7) | (64 + kb)));
            }
            #pragma unroll
            for (int nb = 0; nb < 2; nb++) {
                int row = wn0 + nb * 16 + ((tI >> 1) << 3) + lr;
                int kb = (ks << 5) | ((tI & 1) << 4);
                ldsm_x4(Bh[nb], sb + SWZ((row << 7) | kb));
                ldsm_x4(Bl[nb], sb + SWZ((row << 7) | (64 + kb)));
            }
            #pragma unroll
            for (int ma = 0; ma < 4; ma++)
                #pragma unroll
                for (int na = 0; na < 4; na++) {
                    int nb = na >> 1, off = (na & 1) * 2;
                    mma_bf16(acc[ma][na], Ah[ma], Bl[nb][off], Bl[nb][off + 1]);
                    mma_bf16(acc[ma][na], Al[ma], Bh[nb][off], Bh[nb][off + 1]);
                    mma_bf16(acc[ma][na], Ah[ma], Bh[nb][off], Bh[nb][off + 1]);
                }
        }
        __syncthreads();
    }

    // epilogue
    #pragma unroll
    for (int ma = 0; ma < 4; ma++) {
        int row = bm + wm0 + ma * 16 + (lane >> 2);
        #pragma unroll
        for (int na = 0; na < 4; na++) {
            int col = bn + wn0 + na * 8 + 2 * (lane & 3);
            if (row < M)
                *reinterpret_cast<float2*>(&C[(size_t)row * N + col]) =
                    make_float2(acc[ma][na][0], acc[ma][na][1]);
            if (row + 8 < M)
                *reinterpret_cast<float2*>(&C[(size_t)(row + 8) * N + col]) =
                    make_float2(acc[ma][na][2], acc[ma][na][3]);
        }
    }
}

// ------------- transpose + split: planes[c*R+r] = split(in[r*C + c]) --------
__global__ void k_transpose_split(const float* __restrict__ in, __nv_bfloat16* __restrict__ out,
                                  int R, int Ccols, size_t plane) {
    __shared__ float tile[32][33];
    int c0 = blockIdx.x * 32, r0 = blockIdx.y * 32;
    int x = threadIdx.x, y = threadIdx.y;
    for (int j = 0; j < 32; j += 8) {
        int r = r0 + y + j, c = c0 + x;
        if (r < R && c < Ccols) tile[y + j][x] = in[(size_t)r * Ccols + c];
    }
    __syncthreads();
    for (int j = 0; j < 32; j += 8) {
        int c = c0 + y + j, r = r0 + x;
        if (c < Ccols && r < R) {
            __nv_bfloat16 hi, lo;
            split_bf16(tile[x][y + j], hi, lo);
            out[(size_t)c * R + r] = hi;
            out[plane + (size_t)c * R + r] = lo;
        }
    }
}

// ------------- plain split: planes from fp32 array --------------------------
__global__ void k_split(const float* __restrict__ in, __nv_bfloat16* __restrict__ out, size_t n) {
    size_t i = (size_t)blockIdx.x * blockDim.x + threadIdx.x;
    if (i >= n) return;
    __nv_bfloat16 hi, lo;
    split_bf16(in[i], hi, lo);
    out[i] = hi;
    out[n + i] = lo;
}

// ---------------- utility kernels ----------------
__global__ void k_zero_f(float* p, int n) {
    int i = blockIdx.x * blockDim.x + threadIdx.x;
    if (i < n) p[i] = 0.f;
}
__global__ void k_zero_i(int* p, int n) {
    int i = blockIdx.x * blockDim.x + threadIdx.x;
    if (i < n) p[i] = 0;
}

// ---------------- CSR precompute ----------------
__global__ void k_count(const float* __restrict__ ea, const int* __restrict__ dst,
                        float* degf, float* loopsum, int* cnt) {
    int e = blockIdx.x * blockDim.x + threadIdx.x;
    if (e >= EE) return;
    int d = dst[e];
    atomicAdd(&degf[d], 1.f);
    atomicAdd(&cnt[d], 1);
    atomicAdd(&loopsum[d * 3 + 0], ea[e * 3 + 0]);
    atomicAdd(&loopsum[d * 3 + 1], ea[e * 3 + 1]);
    atomicAdd(&loopsum[d * 3 + 2], ea[e * 3 + 2]);
}

__global__ void k_scan(const int* __restrict__ cnt, int* __restrict__ rowptr) {
    __shared__ int tmp[1024];
    __shared__ int carry_s;
    int tid = threadIdx.x;
    if (tid == 0) { carry_s = 0; rowptr[0] = 0; }
    __syncthreads();
    for (int base = 0; base < NN; base += 1024) {
        int i = base + tid;
        int v = (i < NN) ? (cnt[i] + 1) : 0;
        tmp[tid] = v;
        __syncthreads();
        #pragma unroll
        for (int off = 1; off < 1024; off <<= 1) {
            int tv = (tid >= off) ? tmp[tid - off] : 0;
            __syncthreads();
            tmp[tid] += tv;
            __syncthreads();
        }
        if (i < NN) rowptr[i + 1] = carry_s + tmp[tid];
        __syncthreads();
        if (tid == 0) carry_s += tmp[1023];
        __syncthreads();
    }
}

__global__ void k_scatter_e(const float* __restrict__ ea, const int* __restrict__ src,
                            const int* __restrict__ dst, const int* __restrict__ rowptr,
                            int* fill, int* adj_src, float* adj_ea) {
    int e = blockIdx.x * blockDim.x + threadIdx.x;
    if (e >= EE) return;
    int d = dst[e];
    int pos = rowptr[d] + atomicAdd(&fill[d], 1);
    adj_src[pos] = src[e];
    adj_ea[pos * 3 + 0] = ea[e * 3 + 0];
    adj_ea[pos * 3 + 1] = ea[e * 3 + 1];
    adj_ea[pos * 3 + 2] = ea[e * 3 + 2];
}

__global__ void k_scatter_loop(const float* __restrict__ degf, const float* __restrict__ loopsum,
                               const int* __restrict__ rowptr, int* fill,
                               int* adj_src, float* adj_ea) {
    int n = blockIdx.x * blockDim.x + threadIdx.x;
    if (n >= NN) return;
    int pos = rowptr[n] + atomicAdd(&fill[n], 1);
    adj_src[pos] = n;
    float dm = fmaxf(degf[n], 1.f);
    adj_ea[pos * 3 + 0] = loopsum[n * 3 + 0] / dm;
    adj_ea[pos * 3 + 1] = loopsum[n * 3 + 1] / dm;
    adj_ea[pos * 3 + 2] = loopsum[n * 3 + 2] / dm;
}

// ---------------- fused GATv2 edge kernel (one block per dst node) ----------
// Reads fp32 xl/xr (combined [N, ldx]); writes OUTPUT as bf16 hi/lo planes.
template <int NH>
__global__ void gat_edge(const float* __restrict__ xl, const float* __restrict__ xr,
                         int ldx,
                         const float* __restrict__ we,  const float* __restrict__ att,
                         const float* __restrict__ bias,
                         const int* __restrict__ rowptr, const int* __restrict__ adj_src,
                         const float* __restrict__ adj_ea,
                         __nv_bfloat16* __restrict__ outp, size_t plane) {
    constexpr int F = NH * 64;
    __shared__ float s_xr[F];
    __shared__ float s_part[F / 32];
    int n = blockIdx.x;
    int tid = threadIdx.x;
    int h = tid >> 6;
    int warp = tid >> 5, lane = tid & 31;

    s_xr[tid] = xr[(size_t)n * ldx + tid];
    float attv = att[tid];
    float w0 = we[tid], w1 = we[F + tid], w2 = we[2 * F + tid];
    float bv = bias[tid];
    int beg = rowptr[n], end = rowptr[n + 1];
    float m_run = -1e30f, s_run = 0.f, acc = 0.f;
    __syncthreads();

    for (int p = beg; p < end; ++p) {
        int src = adj_src[p];
        float ea0 = adj_ea[3 * p + 0];
        float ea1 = adj_ea[3 * p + 1];
        float ea2 = adj_ea[3 * p + 2];
        float xlv = __ldg(&xl[(size_t)src * ldx + tid]);
        float m = xlv + s_xr[tid] + ea0 * w0 + ea1 * w1 + ea2 * w2;
        m = (m > 0.f) ? m : 0.2f * m;
        float part = m * attv;
        #pragma unroll
        for (int off = 16; off; off >>= 1)
            part += __shfl_xor_sync(0xffffffffu, part, off);
        if (lane == 0) s_part[warp] = part;
        __syncthreads();
        float logit = s_part[2 * h] + s_part[2 * h + 1];
        float newm = fmaxf(m_run, logit);
        float sc = __expf(m_run - newm);
        float w  = __expf(logit - newm);
        s_run = s_run * sc + w;
        acc   = acc * sc + w * xlv;
        m_run = newm;
        __syncthreads();
    }
    float o = acc / s_run + bv;
    o = (o > 0.f) ? o : (__expf(o) - 1.f);
    __nv_bfloat16 hi, lo;
    split_bf16(o, hi, lo);
    size_t idx = (size_t)n * F + tid;
    outp[idx] = hi;
    outp[plane + idx] = lo;
}

// ---------------- GRU gate kernel (writes fp32 h + bf16 planes) -------------
__global__ void gru_gate(const float* __restrict__ gi, const float* __restrict__ gh,
                         const float* __restrict__ bih, const float* __restrict__ bhh,
                         float* __restrict__ h, __nv_bfloat16* __restrict__ hp) {
    int idx = blockIdx.x * blockDim.x + threadIdx.x;
    if (idx >= NN * GH) return;
    int n = idx / GH, j = idx % GH;
    const float* gin = gi + (size_t)n * G3;
    const float* ghn = gh + (size_t)n * G3;
    float r = 1.f / (1.f + __expf(-(gin[j]      + bih[j]      + ghn[j]      + bhh[j])));
    float z = 1.f / (1.f + __expf(-(gin[GH + j] + bih[GH + j] + ghn[GH + j] + bhh[GH + j])));
    float nv = tanhf(gin[2 * GH + j] + bih[2 * GH + j] + r * (ghn[2 * GH + j] + bhh[2 * GH + j]));
    float hv = h[idx];
    float hn = (1.f - z) * nv + z * hv;
    h[idx] = hn;
    __nv_bfloat16 hi, lo;
    split_bf16(hn, hi, lo);
    hp[idx] = hi;
    hp[NN * GH + idx] = lo;
}

__global__ void k_zero_hplanes(float* h, __nv_bfloat16* hp) {
    int i = blockIdx.x * blockDim.x + threadIdx.x;
    if (i >= NN * GH) return;
    h[i] = 0.f;
    hp[i] = __float2bfloat16(0.f);
    hp[NN * GH + i] = __float2bfloat16(0.f);
}

// ---------------- final reductions ----------------
__global__ void k_colmean(const float* __restrict__ hf, const float* __restrict__ hb,
                          float* __restrict__ mean) {
    int j = blockIdx.x;
    const float* base = (j < GH) ? (hf + j) : (hb + (j - GH));
    float s = 0.f;
    for (int n = threadIdx.x; n < NN; n += blockDim.x) s += base[(size_t)n * GH];
    __shared__ float sh[256];
    sh[threadIdx.x] = s;
    __syncthreads();
    for (int o = 128; o; o >>= 1) {
        if (threadIdx.x < o) sh[threadIdx.x] += sh[threadIdx.x + o];
        __syncthreads();
    }
    if (threadIdx.x == 0) mean[j] = sh[0] * (1.f / (float)NN);
}

__global__ void k_fc(const float* __restrict__ w, const float* __restrict__ b,
                     const float* __restrict__ mean, float* __restrict__ out) {
    int i = blockIdx.x;
    float s = 0.f;
    for (int j = threadIdx.x; j < 2 * GH; j += blockDim.x) s += w[i * 2 * GH + j] * mean[j];
    __shared__ float sh[128];
    sh[threadIdx.x] = s;
    __syncthreads();
    for (int o = 64; o; o >>= 1) {
        if (threadIdx.x < o) sh[threadIdx.x] += sh[threadIdx.x + o];
        __syncthreads();
    }
    if (threadIdx.x == 0) out[i] = sh[0] + b[i];
}

// ---------------- host ----------------
static const int GEMM_SMEM = 2 * 2 * 128 * 128;   // 65536

static void tg(const __nv_bfloat16* Ahi, const __nv_bfloat16* Alo,
               const __nv_bfloat16* Bp, size_t bplane,
               float* C, int M, int N, int K) {
    dim3 g(N / 128, (M + 127) / 128);
    tgemm<<<g, 256, GEMM_SMEM>>>(Ahi, Alo, Bp, Bp + bplane, C, M, N, K);
}

extern "C" void kernel_launch(void* const* d_in, const int* in_sizes, int n_in,
                              void* d_out, int out_size) {
    const float* x        = (const float*)d_in[0];
    const float* edge_ea  = (const float*)d_in[1];
    const int*   edge_src = (const int*)  d_in[2];
    const int*   edge_dst = (const int*)  d_in[3];
    const float* gat1_wl  = (const float*)d_in[4];
    const float* gat1_wr  = (const float*)d_in[5];
    const float* gat1_we  = (const float*)d_in[6];
    const float* gat1_att = (const float*)d_in[7];
    const float* gat1_b   = (const float*)d_in[8];
    const float* gat2_wl  = (const float*)d_in[9];
    const float* gat2_wr  = (const float*)d_in[10];
    const float* gat2_we  = (const float*)d_in[11];
    const float* gat2_att = (const float*)d_in[12];
    const float* gat2_b   = (const float*)d_in[13];
    const float* wih_f    = (const float*)d_in[14];
    const float* whh_f    = (const float*)d_in[15];
    const float* bih_f    = (const float*)d_in[16];
    const float* bhh_f    = (const float*)d_in[17];
    const float* wih_b    = (const float*)d_in[18];
    const float* whh_b    = (const float*)d_in[19];
    const float* bih_b    = (const float*)d_in[20];
    const float* bhh_b    = (const float*)d_in[21];
    const float* fc_w     = (const float*)d_in[22];
    const float* fc_b     = (const float*)d_in[23];
    float* out = (float*)d_out;

    cudaFuncSetAttribute(tgemm, cudaFuncAttributeMaxDynamicSharedMemorySize, GEMM_SMEM);

    float *p_degf, *p_loopsum, *p_adj_ea, *p_xlr1, *p_xlr2;
    float *p_giT, *p_gh, *p_hf, *p_hb, *p_mean;
    int *p_cnt, *p_rowptr, *p_fill, *p_adj_src;
    __nv_bfloat16 *p_xs, *p_w1s, *p_w2s, *p_h1s, *p_embs, *p_hfs, *p_hbs;
    __nv_bfloat16 *p_wihs_f, *p_wihs_b, *p_whhs_f, *p_whhs_b;
    cudaGetSymbolAddress((void**)&p_degf, g_degf);
    cudaGetSymbolAddress((void**)&p_loopsum, g_loopsum);
    cudaGetSymbolAddress((void**)&p_cnt, g_cnt);
    cudaGetSymbolAddress((void**)&p_rowptr, g_rowptr);
    cudaGetSymbolAddress((void**)&p_fill, g_fill);
    cudaGetSymbolAddress((void**)&p_adj_src, g_adj_src);
    cudaGetSymbolAddress((void**)&p_adj_ea, g_adj_ea);
    cudaGetSymbolAddress((void**)&p_xlr1, g_xlr1);
    cudaGetSymbolAddress((void**)&p_xlr2, g_xlr2);
    cudaGetSymbolAddress((void**)&p_giT, g_giT);
    cudaGetSymbolAddress((void**)&p_gh,  g_gh);
    cudaGetSymbolAddress((void**)&p_hf,  g_hf);
    cudaGetSymbolAddress((void**)&p_hb,  g_hb);
    cudaGetSymbolAddress((void**)&p_mean, g_mean);
    cudaGetSymbolAddress((void**)&p_xs,  g_xs);
    cudaGetSymbolAddress((void**)&p_w1s, g_w1s);
    cudaGetSymbolAddress((void**)&p_w2s, g_w2s);
    cudaGetSymbolAddress((void**)&p_h1s, g_h1s);
    cudaGetSymbolAddress((void**)&p_embs, g_embs);
    cudaGetSymbolAddress((void**)&p_hfs, g_hfs);
    cudaGetSymbolAddress((void**)&p_hbs, g_hbs);
    cudaGetSymbolAddress((void**)&p_wihs_f, g_wihs_f);
    cudaGetSymbolAddress((void**)&p_wihs_b, g_wihs_b);
    cudaGetSymbolAddress((void**)&p_whhs_f, g_whhs_f);
    cudaGetSymbolAddress((void**)&p_whhs_b, g_whhs_b);

    const int TB = 256;
    // ---- CSR precompute ----
    k_zero_f<<<(NN + TB - 1) / TB, TB>>>(p_degf, NN);
    k_zero_f<<<(3 * NN + TB - 1) / TB, TB>>>(p_loopsum, 3 * NN);
    k_zero_i<<<(NN + TB - 1) / TB, TB>>>(p_cnt, NN);
    k_count<<<(EE + TB - 1) / TB, TB>>>(edge_ea, edge_dst, p_degf, p_loopsum, p_cnt);
    k_scan<<<1, 1024>>>(p_cnt, p_rowptr);
    k_zero_i<<<(NN + TB - 1) / TB, TB>>>(p_fill, NN);
    k_scatter_e<<<(EE + TB - 1) / TB, TB>>>(edge_ea, edge_src, edge_dst, p_rowptr,
                                            p_fill, p_adj_src, p_adj_ea);
    k_scatter_loop<<<(NN + TB - 1) / TB, TB>>>(p_degf, p_loopsum, p_rowptr,
                                               p_fill, p_adj_src, p_adj_ea);

    // ---- weight transposes + splits into bf16 planes ----
    {
        dim3 b(32, 8);
        size_t pl1 = (size_t)2 * F1 * INC;
        k_transpose_split<<<dim3(F1 / 32, INC / 32), b>>>(gat1_wl, p_w1s, INC, F1, pl1);
        k_transpose_split<<<dim3(F1 / 32, INC / 32), b>>>(gat1_wr, p_w1s + (size_t)F1 * INC, INC, F1, pl1);
        size_t pl2 = (size_t)2 * HIDC * F1;
        k_transpose_split<<<dim3(HIDC / 32, F1 / 32), b>>>(gat2_wl, p_w2s, F1, HIDC, pl2);
        k_transpose_split<<<dim3(HIDC / 32, F1 / 32), b>>>(gat2_wr, p_w2s + (size_t)HIDC * F1, F1, HIDC, pl2);
    }
    // GRU weights are already [N,K]; plain split
    k_split<<<(G3 * HIDC + TB - 1) / TB, TB>>>(wih_f, p_wihs_f, (size_t)G3 * HIDC);
    k_split<<<(G3 * HIDC + TB - 1) / TB, TB>>>(wih_b, p_wihs_b, (size_t)G3 * HIDC);
    k_split<<<(G3 * GH + TB - 1) / TB, TB>>>(whh_f, p_whhs_f, (size_t)G3 * GH);
    k_split<<<(G3 * GH + TB - 1) / TB, TB>>>(whh_b, p_whhs_b, (size_t)G3 * GH);
    // x planes (all T at once)
    {
        size_t nx = (size_t)TT * NN * INC;
        k_split<<<(int)((nx + TB - 1) / TB), TB>>>(x, p_xs, nx);
    }

    const size_t XPL   = (size_t)TT * NN * INC;     // x plane stride
    const size_t H1PL  = (size_t)NN * F1;
    const size_t EMBPL = (size_t)TT * NN * HIDC;
    const size_t W1PL  = (size_t)2 * F1 * INC;
    const size_t W2PL  = (size_t)2 * HIDC * F1;
    const size_t WIHPL = (size_t)G3 * HIDC;
    const size_t WHHPL = (size_t)G3 * GH;

    // ---- per-timestep GAT stack ----
    for (int t = 0; t < TT; t++) {
        const __nv_bfloat16* xhi = p_xs + (size_t)t * NN * INC;
        const __nv_bfloat16* xlo = p_xs + XPL + (size_t)t * NN * INC;
        tgemm<<<dim3((2 * F1) / 128, (NN + 127) / 128), 256, GEMM_SMEM>>>(
            xhi, xlo, p_w1s, p_w1s + W1PL, p_xlr1, NN, 2 * F1, INC);
        gat_edge<NHEADS><<<NN, F1>>>(p_xlr1, p_xlr1 + F1, 2 * F1,
                                     gat1_we, gat1_att, gat1_b,
                                     p_rowptr, p_adj_src, p_adj_ea, p_h1s, H1PL);
        tgemm<<<dim3((2 * HIDC) / 128, (NN + 127) / 128), 256, GEMM_SMEM>>>(
            p_h1s, p_h1s + H1PL, p_w2s, p_w2s + W2PL, p_xlr2, NN, 2 * HIDC, F1);
        gat_edge<1><<<NN, HIDC>>>(p_xlr2, p_xlr2 + HIDC, 2 * HIDC,
                                  gat2_we, gat2_att, gat2_b,
                                  p_rowptr, p_adj_src, p_adj_ea,
                                  p_embs + (size_t)t * NN * HIDC, EMBPL);
    }

    // ---- GRU forward ----
    tgemm<<<dim3(G3 / 128, (TT * NN + 127) / 128), 256, GEMM_SMEM>>>(
        p_embs, p_embs + EMBPL, p_wihs_f, p_wihs_f + WIHPL, p_giT, TT * NN, G3, HIDC);
    k_zero_hplanes<<<(NN * GH + TB - 1) / TB, TB>>>(p_hf, p_hfs);
    for (int t = 0; t < TT; t++) {
        tgemm<<<dim3(G3 / 128, (NN + 127) / 128), 256, GEMM_SMEM>>>(
            p_hfs, p_hfs + NN * GH, p_whhs_f, p_whhs_f + WHHPL, p_gh, NN, G3, GH);
        gru_gate<<<(NN * GH + TB - 1) / TB, TB>>>(p_giT + (size_t)t * NN * G3,
                                                  p_gh, bih_f, bhh_f, p_hf, p_hfs);
    }
    // ---- GRU backward ----
    tgemm<<<dim3(G3 / 128, (TT * NN + 127) / 128), 256, GEMM_SMEM>>>(
        p_embs, p_embs + EMBPL, p_wihs_b, p_wihs_b + WIHPL, p_giT, TT * NN, G3, HIDC);
    k_zero_hplanes<<<(NN * GH + TB - 1) / TB, TB>>>(p_hb, p_hbs);
    for (int tt = 0; tt < TT; tt++) {
        int t = TT - 1 - tt;
        tgemm<<<dim3(G3 / 128, (NN + 127) / 128), 256, GEMM_SMEM>>>(
            p_hbs, p_hbs + NN * GH, p_whhs_b, p_whhs_b + WHHPL, p_gh, NN, G3, GH);
        gru_gate<<<(NN * GH + TB - 1) / TB, TB>>>(p_giT + (size_t)t * NN * G3,
                                                  p_gh, bih_b, bhh_b, p_hb, p_hbs);
    }

    // ---- mean + FC ----
    k_colmean<<<2 * GH, 256>>>(p_hf, p_hb, p_mean);
    k_fc<<<33, 128>>>(fc_w, fc_b, p_mean, out);
}

// round 6
// speedup vs baseline: 2.1958x; 1.4066x over previous
#include <cuda_runtime.h>
#include <cuda_bf16.h>
#include <cstdint>

#define NN     10000
#define EE     160000
#define ENTOT  (EE + NN)
#define TT     32
#define TG     8          // timesteps per GAT chunk
#define INC    128
#define HIDC   64
#define NHEADS 8
#define F1     512        // NHEADS * HID
#define GH     256
#define G3     768        // 3 * GH

// ---------------- scratch (device globals; no allocations allowed) ----------
__device__ float g_degf[NN];
__device__ float g_loopsum[NN * 3];
__device__ int   g_cnt[NN];
__device__ int   g_rowptr[NN + 1];
__device__ int   g_fill[NN];
__device__ int   g_adj_src[ENTOT];
__device__ float g_adj_ea[ENTOT * 3];
__device__ float g_xlr1[(size_t)TG * NN * 2 * F1];   // chunk [TG*N, 1024] = xl|xr
__device__ float g_xlr2[(size_t)TG * NN * 2 * HIDC]; // chunk [TG*N, 128]  = xl|xr
__device__ float g_giF[(size_t)TT * NN * G3];
__device__ float g_giB[(size_t)TT * NN * G3];
__device__ float g_ghF[NN * G3];
__device__ float g_ghB[NN * G3];
__device__ float g_hf[NN * GH];
__device__ float g_hb[NN * GH];
__device__ float g_mean[2 * GH];

// bf16 hi/lo plane buffers: layout [hi(0..n) | lo(n..2n)]
__device__ __nv_bfloat16 g_xs  [(size_t)2 * TT * NN * INC];
__device__ __nv_bfloat16 g_w1s [2 * 2 * F1 * INC];
__device__ __nv_bfloat16 g_w2s [2 * 2 * HIDC * F1];
__device__ __nv_bfloat16 g_h1s [(size_t)2 * TG * NN * F1];     // chunk planes
__device__ __nv_bfloat16 g_embs[(size_t)2 * TT * NN * HIDC];
__device__ __nv_bfloat16 g_hfs [2 * NN * GH];
__device__ __nv_bfloat16 g_hbs [2 * NN * GH];
__device__ __nv_bfloat16 g_wihs_f[2 * G3 * HIDC];
__device__ __nv_bfloat16 g_wihs_b[2 * G3 * HIDC];
__device__ __nv_bfloat16 g_whhs_f[2 * G3 * GH];
__device__ __nv_bfloat16 g_whhs_b[2 * G3 * GH];

// ---------------- helpers ----------------
#define SWZ(off) ((off) ^ (((off) >> 3) & 0x70))

__device__ __forceinline__ uint32_t smem_u32(const void* p) {
    uint32_t a;
    asm("{ .reg .u64 t; cvta.to.shared.u64 t, %1; cvt.u32.u64 %0, t; }" : "=r"(a) : "l"(p));
    return a;
}
__device__ __forceinline__ void cp_async16(uint32_t dst, const void* src, int sz) {
    asm volatile("cp.async.ca.shared.global [%0], [%1], 16, %2;"
                 :: "r"(dst), "l"(src), "r"(sz) : "memory");
}
__device__ __forceinline__ void cp_commit() {
    asm volatile("cp.async.commit_group;" ::: "memory");
}
__device__ __forceinline__ void cp_wait1() {
    asm volatile("cp.async.wait_group 1;" ::: "memory");
}
__device__ __forceinline__ void cp_wait0() {
    asm volatile("cp.async.wait_group 0;" ::: "memory");
}
__device__ __forceinline__ void ldsm_x4(uint32_t* r, uint32_t addr) {
    asm volatile("ldmatrix.sync.aligned.m8n8.x4.shared.b16 {%0,%1,%2,%3}, [%4];"
                 : "=r"(r[0]), "=r"(r[1]), "=r"(r[2]), "=r"(r[3]) : "r"(addr));
}
__device__ __forceinline__ void mma_bf16(float* c, const uint32_t* a, uint32_t b0, uint32_t b1) {
    asm volatile("mma.sync.aligned.m16n8k16.row.col.f32.bf16.bf16.f32 "
                 "{%0,%1,%2,%3}, {%4,%5,%6,%7}, {%8,%9}, {%0,%1,%2,%3};"
                 : "+f"(c[0]), "+f"(c[1]), "+f"(c[2]), "+f"(c[3])
                 : "r"(a[0]), "r"(a[1]), "r"(a[2]), "r"(a[3]), "r"(b0), "r"(b1));
}
__device__ __forceinline__ void split_bf16(float v, __nv_bfloat16& hi, __nv_bfloat16& lo) {
    hi = __float2bfloat16_rn(v);
    lo = __float2bfloat16_rn(v - __bfloat162float(hi));
}

// ---- bf16x3 emulated-fp32 GEMM body: C[M,N] = A[M,K] @ BT[N,K]^T ------------
// A, B pre-split bf16 hi/lo planes ([M,K] bf16 each). BM=128, BN=128, BK=32.
// smem row (128B) = [hi 64B | lo 64B], SW128. 8 warps (2Mx4N), warp tile 64x32.
__device__ __forceinline__ void gemm_body(
    const __nv_bfloat16* __restrict__ Ahi, const __nv_bfloat16* __restrict__ Alo,
    const __nv_bfloat16* __restrict__ Bhi, const __nv_bfloat16* __restrict__ Blo,
    float* __restrict__ C, int M, int N, int K, char* smem)
{
    constexpr int TSZ   = 128 * 128;
    constexpr int STAGE = 2 * TSZ;
    const uint32_t sbase = smem_u32(smem);
    const int t = threadIdx.x;
    const int warp = t >> 5, lane = t & 31;
    const int tI = lane >> 3, lr = lane & 7;
    const int wm0 = (warp & 1) * 64;
    const int wn0 = (warp >> 1) * 32;
    const int bm = blockIdx.y * 128;
    const int bn = blockIdx.x * 128;
    const size_t Kb = (size_t)K * 2;

    float acc[4][4][4];
    #pragma unroll
    for (int i = 0; i < 4; i++)
        #pragma unroll
        for (int j = 0; j < 4; j++)
            #pragma unroll
            for (int k = 0; k < 4; k++) acc[i][j][k] = 0.f;

    const int NC = K >> 5;

    auto load_stage = [&](int s, int c) {
        uint32_t sa = sbase + s * STAGE;
        uint32_t sb = sa + TSZ;
        int k0b = c << 6;
        #pragma unroll
        for (int i = 0; i < 4; i++) {
            int idx = t + i * 256;
            int row = idx >> 3, c8 = idx & 7;
            const char* base = (const char*)((c8 & 4) ? Alo : Ahi);
            const char* src = base + (size_t)(bm + row) * Kb + k0b + (c8 & 3) * 16;
            int sz = (bm + row < M) ? 16 : 0;
            cp_async16(sa + SWZ((row << 7) | (c8 << 4)), src, sz);
        }
        #pragma unroll
        for (int i = 0; i < 4; i++) {
            int idx = t + i * 256;
            int row = idx >> 3, c8 = idx & 7;
            const char* base = (const char*)((c8 & 4) ? Blo : Bhi);
            const char* src = base + (size_t)(bn + row) * Kb + k0b + (c8 & 3) * 16;
            cp_async16(sb + SWZ((row << 7) | (c8 << 4)), src, 16);
        }
        cp_commit();
    };

    load_stage(0, 0);

    for (int c = 0; c < NC; c++) {
        if (c + 1 < NC) { load_stage((c + 1) & 1, c + 1); cp_wait1(); }
        else            { cp_wait0(); }
        __syncthreads();

        uint32_t sa = sbase + (c & 1) * STAGE;
        uint32_t sb = sa + TSZ;
        #pragma unroll
        for (int ks = 0; ks < 2; ks++) {
            uint32_t Ah[4][4], Al[4][4], Bh[2][4], Bl[2][4];
            #pragma unroll
            for (int ma = 0; ma < 4; ma++) {
                int row = wm0 + ma * 16 + ((tI & 1) << 3) + lr;
                int kb = (ks << 5) | ((tI >> 1) << 4);
                ldsm_x4(Ah[ma], sa + SWZ((row << 7) | kb));
                ldsm_x4(Al[ma], sa + SWZ((row << 7) | (64 + kb)));
            }
            #pragma unroll
            for (int nb = 0; nb < 2; nb++) {
                int row = wn0 + nb * 16 + ((tI >> 1) << 3) + lr;
                int kb = (ks << 5) | ((tI & 1) << 4);
                ldsm_x4(Bh[nb], sb + SWZ((row << 7) | kb));
                ldsm_x4(Bl[nb], sb + SWZ((row << 7) | (64 + kb)));
            }
            #pragma unroll
            for (int ma = 0; ma < 4; ma++)
                #pragma unroll
                for (int na = 0; na < 4; na++) {
                    int nb = na >> 1, off = (na & 1) * 2;
                    mma_bf16(acc[ma][na], Ah[ma], Bl[nb][off], Bl[nb][off + 1]);
                    mma_bf16(acc[ma][na], Al[ma], Bh[nb][off], Bh[nb][off + 1]);
                    mma_bf16(acc[ma][na], Ah[ma], Bh[nb][off], Bh[nb][off + 1]);
                }
        }
        __syncthreads();
    }

    #pragma unroll
    for (int ma = 0; ma < 4; ma++) {
        int row = bm + wm0 + ma * 16 + (lane >> 2);
        #pragma unroll
        for (int na = 0; na < 4; na++) {
            int col = bn + wn0 + na * 8 + 2 * (lane & 3);
            if (row < M)
                *reinterpret_cast<float2*>(&C[(size_t)row * N + col]) =
                    make_float2(acc[ma][na][0], acc[ma][na][1]);
            if (row + 8 < M)
                *reinterpret_cast<float2*>(&C[(size_t)(row + 8) * N + col]) =
                    make_float2(acc[ma][na][2], acc[ma][na][3]);
        }
    }
}

__global__ void __launch_bounds__(256) tgemm(
    const __nv_bfloat16* __restrict__ Ahi, const __nv_bfloat16* __restrict__ Alo,
    const __nv_bfloat16* __restrict__ Bhi, const __nv_bfloat16* __restrict__ Blo,
    float* __restrict__ C, int M, int N, int K)
{
    extern __shared__ char smem[];
    gemm_body(Ahi, Alo, Bhi, Blo, C, M, N, K, smem);
}

// z-batched variant: blockIdx.z selects pointer set (fwd / bwd direction)
__global__ void __launch_bounds__(256) tgemm_b2(
    const __nv_bfloat16* Ahi0, const __nv_bfloat16* Alo0,
    const __nv_bfloat16* Bhi0, const __nv_bfloat16* Blo0, float* C0,
    const __nv_bfloat16* Ahi1, const __nv_bfloat16* Alo1,
    const __nv_bfloat16* Bhi1, const __nv_bfloat16* Blo1, float* C1,
    int M, int N, int K)
{
    extern __shared__ char smem[];
    if (blockIdx.z == 0) gemm_body(Ahi0, Alo0, Bhi0, Blo0, C0, M, N, K, smem);
    else                 gemm_body(Ahi1, Alo1, Bhi1, Blo1, C1, M, N, K, smem);
}

// ------------- transpose + split: planes[c*R+r] = split(in[r*C + c]) --------
__global__ void k_transpose_split(const float* __restrict__ in, __nv_bfloat16* __restrict__ out,
                                  int R, int Ccols, size_t plane) {
    __shared__ float tile[32][33];
    int c0 = blockIdx.x * 32, r0 = blockIdx.y * 32;
    int x = threadIdx.x, y = threadIdx.y;
    for (int j = 0; j < 32; j += 8) {
        int r = r0 + y + j, c = c0 + x;
        if (r < R && c < Ccols) tile[y + j][x] = in[(size_t)r * Ccols + c];
    }
    __syncthreads();
    for (int j = 0; j < 32; j += 8) {
        int c = c0 + y + j, r = r0 + x;
        if (c < Ccols && r < R) {
            __nv_bfloat16 hi, lo;
            split_bf16(tile[x][y + j], hi, lo);
            out[(size_t)c * R + r] = hi;
            out[plane + (size_t)c * R + r] = lo;
        }
    }
}

__global__ void k_split(const float* __restrict__ in, __nv_bfloat16* __restrict__ out, size_t n) {
    size_t i = (size_t)blockIdx.x * blockDim.x + threadIdx.x;
    if (i >= n) return;
    __nv_bfloat16 hi, lo;
    split_bf16(in[i], hi, lo);
    out[i] = hi;
    out[n + i] = lo;
}

// ---------------- utility kernels ----------------
__global__ void k_zero_f(float* p, int n) {
    int i = blockIdx.x * blockDim.x + threadIdx.x;
    if (i < n) p[i] = 0.f;
}
__global__ void k_zero_i(int* p, int n) {
    int i = blockIdx.x * blockDim.x + threadIdx.x;
    if (i < n) p[i] = 0;
}

// ---------------- CSR precompute ----------------
__global__ void k_count(const float* __restrict__ ea, const int* __restrict__ dst,
                        float* degf, float* loopsum, int* cnt) {
    int e = blockIdx.x * blockDim.x + threadIdx.x;
    if (e >= EE) return;
    int d = dst[e];
    atomicAdd(&degf[d], 1.f);
    atomicAdd(&cnt[d], 1);
    atomicAdd(&loopsum[d * 3 + 0], ea[e * 3 + 0]);
    atomicAdd(&loopsum[d * 3 + 1], ea[e * 3 + 1]);
    atomicAdd(&loopsum[d * 3 + 2], ea[e * 3 + 2]);
}

__global__ void k_scan(const int* __restrict__ cnt, int* __restrict__ rowptr) {
    __shared__ int tmp[1024];
    __shared__ int carry_s;
    int tid = threadIdx.x;
    if (tid == 0) { carry_s = 0; rowptr[0] = 0; }
    __syncthreads();
    for (int base = 0; base < NN; base += 1024) {
        int i = base + tid;
        int v = (i < NN) ? (cnt[i] + 1) : 0;
        tmp[tid] = v;
        __syncthreads();
        #pragma unroll
        for (int off = 1; off < 1024; off <<= 1) {
            int tv = (tid >= off) ? tmp[tid - off] : 0;
            __syncthreads();
            tmp[tid] += tv;
            __syncthreads();
        }
        if (i < NN) rowptr[i + 1] = carry_s + tmp[tid];
        __syncthreads();
        if (tid == 0) carry_s += tmp[1023];
        __syncthreads();
    }
}

__global__ void k_scatter_e(const float* __restrict__ ea, const int* __restrict__ src,
                            const int* __restrict__ dst, const int* __restrict__ rowptr,
                            int* fill, int* adj_src, float* adj_ea) {
    int e = blockIdx.x * blockDim.x + threadIdx.x;
    if (e >= EE) return;
    int d = dst[e];
    int pos = rowptr[d] + atomicAdd(&fill[d], 1);
    adj_src[pos] = src[e];
    adj_ea[pos * 3 + 0] = ea[e * 3 + 0];
    adj_ea[pos * 3 + 1] = ea[e * 3 + 1];
    adj_ea[pos * 3 + 2] = ea[e * 3 + 2];
}

__global__ void k_scatter_loop(const float* __restrict__ degf, const float* __restrict__ loopsum,
                               const int* __restrict__ rowptr, int* fill,
                               int* adj_src, float* adj_ea) {
    int n = blockIdx.x * blockDim.x + threadIdx.x;
    if (n >= NN) return;
    int pos = rowptr[n] + atomicAdd(&fill[n], 1);
    adj_src[pos] = n;
    float dm = fmaxf(degf[n], 1.f);
    adj_ea[pos * 3 + 0] = loopsum[n * 3 + 0] / dm;
    adj_ea[pos * 3 + 1] = loopsum[n * 3 + 1] / dm;
    adj_ea[pos * 3 + 2] = loopsum[n * 3 + 2] / dm;
}

// ---- GAT1 edge kernel: barrier-free, warp == head, batched over chunk t ----
// grid (NN, TG), block 256 (8 warps = 8 heads). xlr chunk [TG*N, 1024].
__global__ void __launch_bounds__(256) gat_edge1(
    const float* __restrict__ xlr,
    const float* __restrict__ we, const float* __restrict__ att,
    const float* __restrict__ bias,
    const int* __restrict__ rowptr, const int* __restrict__ adj_src,
    const float* __restrict__ adj_ea,
    __nv_bfloat16* __restrict__ outp)
{
    constexpr size_t H1PL = (size_t)TG * NN * F1;
    int n = blockIdx.x, tc = blockIdx.y;
    int warp = threadIdx.x >> 5, lane = threadIdx.x & 31;
    int c0 = warp * 64 + lane, c1 = c0 + 32;
    const float* base = xlr + (size_t)tc * NN * (2 * F1);
    const float* xrrow = base + (size_t)n * (2 * F1) + F1;
    float xr0 = xrrow[c0], xr1 = xrrow[c1];
    float a0 = att[c0], a1 = att[c1];
    float w00 = we[c0], w01 = we[F1 + c0], w02 = we[2 * F1 + c0];
    float w10 = we[c1], w11 = we[F1 + c1], w12 = we[2 * F1 + c1];
    int beg = rowptr[n], end = rowptr[n + 1];
    float m_run = -1e30f, s_run = 0.f, acc0 = 0.f, acc1 = 0.f;

    int src_n = adj_src[beg];
    float e0n = adj_ea[3 * beg], e1n = adj_ea[3 * beg + 1], e2n = adj_ea[3 * beg + 2];
    const float* rp = base + (size_t)src_n * (2 * F1);
    float x0n = rp[c0], x1n = rp[c1];

    for (int p = beg; p < end; p++) {
        float x0 = x0n, x1 = x1n, e0 = e0n, e1 = e1n, e2 = e2n;
        if (p + 1 < end) {
            int s2 = adj_src[p + 1];
            e0n = adj_ea[3 * (p + 1)]; e1n = adj_ea[3 * (p + 1) + 1]; e2n = adj_ea[3 * (p + 1) + 2];
            const float* rp2 = base + (size_t)s2 * (2 * F1);
            x0n = rp2[c0]; x1n = rp2[c1];
        }
        float m0 = x0 + xr0 + e0 * w00 + e1 * w01 + e2 * w02;
        float m1 = x1 + xr1 + e0 * w10 + e1 * w11 + e2 * w12;
        m0 = (m0 > 0.f) ? m0 : 0.2f * m0;
        m1 = (m1 > 0.f) ? m1 : 0.2f * m1;
        float part = m0 * a0 + m1 * a1;
        #pragma unroll
        for (int o = 16; o; o >>= 1) part += __shfl_xor_sync(0xffffffffu, part, o);
        float newm = fmaxf(m_run, part);
        float sc = __expf(m_run - newm), w = __expf(part - newm);
        s_run = s_run * sc + w;
        acc0 = acc0 * sc + w * x0;
        acc1 = acc1 * sc + w * x1;
        m_run = newm;
    }
    float inv = 1.f / s_run;
    float o0 = acc0 * inv + bias[c0];
    float o1 = acc1 * inv + bias[c1];
    o0 = (o0 > 0.f) ? o0 : (__expf(o0) - 1.f);
    o1 = (o1 > 0.f) ? o1 : (__expf(o1) - 1.f);
    size_t orow = ((size_t)tc * NN + n) * F1;
    __nv_bfloat16 hi, lo;
    split_bf16(o0, hi, lo); outp[orow + c0] = hi; outp[H1PL + orow + c0] = lo;
    split_bf16(o1, hi, lo); outp[orow + c1] = hi; outp[H1PL + orow + c1] = lo;
}

// ---- GAT2 edge kernel: warp == node (1 head), batched over chunk t ---------
// grid (NN/8, TG), block 256 (8 warps = 8 nodes). xlr chunk [TG*N, 128].
__global__ void __launch_bounds__(256) gat_edge2(
    const float* __restrict__ xlr,
    const float* __restrict__ we, const float* __restrict__ att,
    const float* __restrict__ bias,
    const int* __restrict__ rowptr, const int* __restrict__ adj_src,
    const float* __restrict__ adj_ea,
    __nv_bfloat16* __restrict__ outp)  // pre-offset by t0*NN*HIDC
{
    constexpr size_t EMBPL = (size_t)TT * NN * HIDC;
    int warp = threadIdx.x >> 5, lane = threadIdx.x & 31;
    int n = blockIdx.x * 8 + warp, tc = blockIdx.y;
    int c0 = lane, c1 = lane + 32;
    const float* base = xlr + (size_t)tc * NN * (2 * HIDC);
    const float* xrrow = base + (size_t)n * (2 * HIDC) + HIDC;
    float xr0 = xrrow[c0], xr1 = xrrow[c1];
    float a0 = att[c0], a1 = att[c1];
    float w00 = we[c0], w01 = we[HIDC + c0], w02 = we[2 * HIDC + c0];
    float w10 = we[c1], w11 = we[HIDC + c1], w12 = we[2 * HIDC + c1];
    int beg = rowptr[n], end = rowptr[n + 1];
    float m_run = -1e30f, s_run = 0.f, acc0 = 0.f, acc1 = 0.f;

    int src_n = adj_src[beg];
    float e0n = adj_ea[3 * beg], e1n = adj_ea[3 * beg + 1], e2n = adj_ea[3 * beg + 2];
    const float* rp = base + (size_t)src_n * (2 * HIDC);
    float x0n = rp[c0], x1n = rp[c1];

    for (int p = beg; p < end; p++) {
        float x0 = x0n, x1 = x1n, e0 = e0n, e1 = e1n, e2 = e2n;
        if (p + 1 < end) {
            int s2 = adj_src[p + 1];
            e0n = adj_ea[3 * (p + 1)]; e1n = adj_ea[3 * (p + 1) + 1]; e2n = adj_ea[3 * (p + 1) + 2];
            const float* rp2 = base + (size_t)s2 * (2 * HIDC);
            x0n = rp2[c0]; x1n = rp2[c1];
        }
        float m0 = x0 + xr0 + e0 * w00 + e1 * w01 + e2 * w02;
        float m1 = x1 + xr1 + e0 * w10 + e1 * w11 + e2 * w12;
        m0 = (m0 > 0.f) ? m0 : 0.2f * m0;
        m1 = (m1 > 0.f) ? m1 : 0.2f * m1;
        float part = m0 * a0 + m1 * a1;
        #pragma unroll
        for (int o = 16; o; o >>= 1) part += __shfl_xor_sync(0xffffffffu, part, o);
        float newm = fmaxf(m_run, part);
        float sc = __expf(m_run - newm), w = __expf(part - newm);
        s_run = s_run * sc + w;
        acc0 = acc0 * sc + w * x0;
        acc1 = acc1 * sc + w * x1;
        m_run = newm;
    }
    float inv = 1.f / s_run;
    float o0 = acc0 * inv + bias[c0];
    float o1 = acc1 * inv + bias[c1];
    o0 = (o0 > 0.f) ? o0 : (__expf(o0) - 1.f);
    o1 = (o1 > 0.f) ? o1 : (__expf(o1) - 1.f);
    size_t orow = ((size_t)tc * NN + n) * HIDC;
    __nv_bfloat16 hi, lo;
    split_bf16(o0, hi, lo); outp[orow + c0] = hi; outp[EMBPL + orow + c0] = lo;
    split_bf16(o1, hi, lo); outp[orow + c1] = hi; outp[EMBPL + orow + c1] = lo;
}

// ---------------- GRU gate kernel, both directions in one launch ------------
__global__ void gru_gate2(const float* __restrict__ giF, const float* __restrict__ giB,
                          const float* __restrict__ ghF, const float* __restrict__ ghB,
                          const float* __restrict__ bihf, const float* __restrict__ bhhf,
                          const float* __restrict__ bihb, const float* __restrict__ bhhb,
                          float* __restrict__ hF, float* __restrict__ hB,
                          __nv_bfloat16* __restrict__ hFs, __nv_bfloat16* __restrict__ hBs) {
    int dir = blockIdx.y;
    const float* gi  = dir ? giB : giF;
    const float* gh  = dir ? ghB : ghF;
    const float* bih = dir ? bihb : bihf;
    const float* bhh = dir ? bhhb : bhhf;
    float* h = dir ? hB : hF;
    __nv_bfloat16* hp = dir ? hBs : hFs;
    int idx = blockIdx.x * blockDim.x + threadIdx.x;
    if (idx >= NN * GH) return;
    int n = idx / GH, j = idx % GH;
    const float* gin = gi + (size_t)n * G3;
    const float* ghn = gh + (size_t)n * G3;
    float r = 1.f / (1.f + __expf(-(gin[j]      + bih[j]      + ghn[j]      + bhh[j])));
    float z = 1.f / (1.f + __expf(-(gin[GH + j] + bih[GH + j] + ghn[GH + j] + bhh[GH + j])));
    float nv = tanhf(gin[2 * GH + j] + bih[2 * GH + j] + r * (ghn[2 * GH + j] + bhh[2 * GH + j]));
    float hv = h[idx];
    float hn = (1.f - z) * nv + z * hv;
    h[idx] = hn;
    __nv_bfloat16 hi, lo;
    split_bf16(hn, hi, lo);
    hp[idx] = hi;
    hp[NN * GH + idx] = lo;
}

__global__ void k_zero_hplanes(float* h, __nv_bfloat16* hp) {
    int i = blockIdx.x * blockDim.x + threadIdx.x;
    if (i >= NN * GH) return;
    h[i] = 0.f;
    hp[i] = __float2bfloat16(0.f);
    hp[NN * GH + i] = __float2bfloat16(0.f);
}

// ---------------- final reductions ----------------
__global__ void k_colmean(const float* __restrict__ hf, const float* __restrict__ hb,
                          float* __restrict__ mean) {
    int j = blockIdx.x;
    const float* base = (j < GH) ? (hf + j) : (hb + (j - GH));
    float s = 0.f;
    for (int n = threadIdx.x; n < NN; n += blockDim.x) s += base[(size_t)n * GH];
    __shared__ float sh[256];
    sh[threadIdx.x] = s;
    __syncthreads();
    for (int o = 128; o; o >>= 1) {
        if (threadIdx.x < o) sh[threadIdx.x] += sh[threadIdx.x + o];
        __syncthreads();
    }
    if (threadIdx.x == 0) mean[j] = sh[0] * (1.f / (float)NN);
}

__global__ void k_fc(const float* __restrict__ w, const float* __restrict__ b,
                     const float* __restrict__ mean, float* __restrict__ out) {
    int i = blockIdx.x;
    float s = 0.f;
    for (int j = threadIdx.x; j < 2 * GH; j += blockDim.x) s += w[i * 2 * GH + j] * mean[j];
    __shared__ float sh[128];
    sh[threadIdx.x] = s;
    __syncthreads();
    for (int o = 64; o; o >>= 1) {
        if (threadIdx.x < o) sh[threadIdx.x] += sh[threadIdx.x + o];
        __syncthreads();
    }
    if (threadIdx.x == 0) out[i] = sh[0] + b[i];
}

// ---------------- host ----------------
static const int GEMM_SMEM = 2 * 2 * 128 * 128;   // 65536

extern "C" void kernel_launch(void* const* d_in, const int* in_sizes, int n_in,
                              void* d_out, int out_size) {
    const float* x        = (const float*)d_in[0];
    const float* edge_ea  = (const float*)d_in[1];
    const int*   edge_src = (const int*)  d_in[2];
    const int*   edge_dst = (const int*)  d_in[3];
    const float* gat1_wl  = (const float*)d_in[4];
    const float* gat1_wr  = (const float*)d_in[5];
    const float* gat1_we  = (const float*)d_in[6];
    const float* gat1_att = (const float*)d_in[7];
    const float* gat1_b   = (const float*)d_in[8];
    const float* gat2_wl  = (const float*)d_in[9];
    const float* gat2_wr  = (const float*)d_in[10];
    const float* gat2_we  = (const float*)d_in[11];
    const float* gat2_att = (const float*)d_in[12];
    const float* gat2_b   = (const float*)d_in[13];
    const float* wih_f    = (const float*)d_in[14];
    const float* whh_f    = (const float*)d_in[15];
    const float* bih_f    = (const float*)d_in[16];
    const float* bhh_f    = (const float*)d_in[17];
    const float* wih_b    = (const float*)d_in[18];
    const float* whh_b    = (const float*)d_in[19];
    const float* bih_b    = (const float*)d_in[20];
    const float* bhh_b    = (const float*)d_in[21];
    const float* fc_w     = (const float*)d_in[22];
    const float* fc_b     = (const float*)d_in[23];
    float* out = (float*)d_out;

    cudaFuncSetAttribute(tgemm, cudaFuncAttributeMaxDynamicSharedMemorySize, GEMM_SMEM);
    cudaFuncSetAttribute(tgemm_b2, cudaFuncAttributeMaxDynamicSharedMemorySize, GEMM_SMEM);

    float *p_degf, *p_loopsum, *p_adj_ea, *p_xlr1, *p_xlr2;
    float *p_giF, *p_giB, *p_ghF, *p_ghB, *p_hf, *p_hb, *p_mean;
    int *p_cnt, *p_rowptr, *p_fill, *p_adj_src;
    __nv_bfloat16 *p_xs, *p_w1s, *p_w2s, *p_h1s, *p_embs, *p_hfs, *p_hbs;
    __nv_bfloat16 *p_wihs_f, *p_wihs_b, *p_whhs_f, *p_whhs_b;
    cudaGetSymbolAddress((void**)&p_degf, g_degf);
    cudaGetSymbolAddress((void**)&p_loopsum, g_loopsum);
    cudaGetSymbolAddress((void**)&p_cnt, g_cnt);
    cudaGetSymbolAddress((void**)&p_rowptr, g_rowptr);
    cudaGetSymbolAddress((void**)&p_fill, g_fill);
    cudaGetSymbolAddress((void**)&p_adj_src, g_adj_src);
    cudaGetSymbolAddress((void**)&p_adj_ea, g_adj_ea);
    cudaGetSymbolAddress((void**)&p_xlr1, g_xlr1);
    cudaGetSymbolAddress((void**)&p_xlr2, g_xlr2);
    cudaGetSymbolAddress((void**)&p_giF, g_giF);
    cudaGetSymbolAddress((void**)&p_giB, g_giB);
    cudaGetSymbolAddress((void**)&p_ghF, g_ghF);
    cudaGetSymbolAddress((void**)&p_ghB, g_ghB);
    cudaGetSymbolAddress((void**)&p_hf,  g_hf);
    cudaGetSymbolAddress((void**)&p_hb,  g_hb);
    cudaGetSymbolAddress((void**)&p_mean, g_mean);
    cudaGetSymbolAddress((void**)&p_xs,  g_xs);
    cudaGetSymbolAddress((void**)&p_w1s, g_w1s);
    cudaGetSymbolAddress((void**)&p_w2s, g_w2s);
    cudaGetSymbolAddress((void**)&p_h1s, g_h1s);
    cudaGetSymbolAddress((void**)&p_embs, g_embs);
    cudaGetSymbolAddress((void**)&p_hfs, g_hfs);
    cudaGetSymbolAddress((void**)&p_hbs, g_hbs);
    cudaGetSymbolAddress((void**)&p_wihs_f, g_wihs_f);
    cudaGetSymbolAddress((void**)&p_wihs_b, g_wihs_b);
    cudaGetSymbolAddress((void**)&p_whhs_f, g_whhs_f);
    cudaGetSymbolAddress((void**)&p_whhs_b, g_whhs_b);

    const int TB = 256;
    // ---- CSR precompute ----
    k_zero_f<<<(NN + TB - 1) / TB, TB>>>(p_degf, NN);
    k_zero_f<<<(3 * NN + TB - 1) / TB, TB>>>(p_loopsum, 3 * NN);
    k_zero_i<<<(NN + TB - 1) / TB, TB>>>(p_cnt, NN);
    k_count<<<(EE + TB - 1) / TB, TB>>>(edge_ea, edge_dst, p_degf, p_loopsum, p_cnt);
    k_scan<<<1, 1024>>>(p_cnt, p_rowptr);
    k_zero_i<<<(NN + TB - 1) / TB, TB>>>(p_fill, NN);
    k_scatter_e<<<(EE + TB - 1) / TB, TB>>>(edge_ea, edge_src, edge_dst, p_rowptr,
                                            p_fill, p_adj_src, p_adj_ea);
    k_scatter_loop<<<(NN + TB - 1) / TB, TB>>>(p_degf, p_loopsum, p_rowptr,
                                               p_fill, p_adj_src, p_adj_ea);

    // ---- weight transposes + splits into bf16 planes ----
    {
        dim3 b(32, 8);
        size_t pl1 = (size_t)2 * F1 * INC;
        k_transpose_split<<<dim3(F1 / 32, INC / 32), b>>>(gat1_wl, p_w1s, INC, F1, pl1);
        k_transpose_split<<<dim3(F1 / 32, INC / 32), b>>>(gat1_wr, p_w1s + (size_t)F1 * INC, INC, F1, pl1);
        size_t pl2 = (size_t)2 * HIDC * F1;
        k_transpose_split<<<dim3(HIDC / 32, F1 / 32), b>>>(gat2_wl, p_w2s, F1, HIDC, pl2);
        k_transpose_split<<<dim3(HIDC / 32, F1 / 32), b>>>(gat2_wr, p_w2s + (size_t)HIDC * F1, F1, HIDC, pl2);
    }
    k_split<<<(G3 * HIDC + TB - 1) / TB, TB>>>(wih_f, p_wihs_f, (size_t)G3 * HIDC);
    k_split<<<(G3 * HIDC + TB - 1) / TB, TB>>>(wih_b, p_wihs_b, (size_t)G3 * HIDC);
    k_split<<<(G3 * GH + TB - 1) / TB, TB>>>(whh_f, p_whhs_f, (size_t)G3 * GH);
    k_split<<<(G3 * GH + TB - 1) / TB, TB>>>(whh_b, p_whhs_b, (size_t)G3 * GH);
    {
        size_t nx = (size_t)TT * NN * INC;
        k_split<<<(int)((nx + TB - 1) / TB), TB>>>(x, p_xs, nx);
    }

    const size_t XPL   = (size_t)TT * NN * INC;
    const size_t H1PL  = (size_t)TG * NN * F1;
    const size_t EMBPL = (size_t)TT * NN * HIDC;
    const size_t W1PL  = (size_t)2 * F1 * INC;
    const size_t W2PL  = (size_t)2 * HIDC * F1;
    const size_t WIHPL = (size_t)G3 * HIDC;
    const size_t WHHPL = (size_t)G3 * GH;

    // ---- GAT phase: 4 chunks of TG=8 timesteps, batched ----
    for (int ch = 0; ch < TT / TG; ch++) {
        int t0 = ch * TG;
        tgemm<<<dim3((2 * F1) / 128, (TG * NN + 127) / 128), 256, GEMM_SMEM>>>(
            p_xs + (size_t)t0 * NN * INC, p_xs + XPL + (size_t)t0 * NN * INC,
            p_w1s, p_w1s + W1PL, p_xlr1, TG * NN, 2 * F1, INC);
        gat_edge1<<<dim3(NN, TG), 256>>>(p_xlr1, gat1_we, gat1_att, gat1_b,
                                         p_rowptr, p_adj_src, p_adj_ea, p_h1s);
        tgemm<<<dim3(1, (TG * NN + 127) / 128), 256, GEMM_SMEM>>>(
            p_h1s, p_h1s + H1PL, p_w2s, p_w2s + W2PL, p_xlr2, TG * NN, 2 * HIDC, F1);
        gat_edge2<<<dim3(NN / 8, TG), 256>>>(p_xlr2, gat2_we, gat2_att, gat2_b,
                                             p_rowptr, p_adj_src, p_adj_ea,
                                             p_embs + (size_t)t0 * NN * HIDC);
    }

    // ---- batched gi GEMMs (both directions, all T) ----
    tgemm_b2<<<dim3(G3 / 128, (TT * NN + 127) / 128, 2), 256, GEMM_SMEM>>>(
        p_embs, p_embs + EMBPL, p_wihs_f, p_wihs_f + WIHPL, p_giF,
        p_embs, p_embs + EMBPL, p_wihs_b, p_wihs_b + WIHPL, p_giB,
        TT * NN, G3, HIDC);

    // ---- GRU chain: fwd + bwd batched per step ----
    k_zero_hplanes<<<(NN * GH + TB - 1) / TB, TB>>>(p_hf, p_hfs);
    k_zero_hplanes<<<(NN * GH + TB - 1) / TB, TB>>>(p_hb, p_hbs);
    for (int t = 0; t < TT; t++) {
        tgemm_b2<<<dim3(G3 / 128, (NN + 127) / 128, 2), 256, GEMM_SMEM>>>(
            p_hfs, p_hfs + NN * GH, p_whhs_f, p_whhs_f + WHHPL, p_ghF,
            p_hbs, p_hbs + NN * GH, p_whhs_b, p_whhs_b + WHHPL, p_ghB,
            NN, G3, GH);
        gru_gate2<<<dim3((NN * GH + TB - 1) / TB, 2), TB>>>(
            p_giF + (size_t)t * NN * G3, p_giB + (size_t)(TT - 1 - t) * NN * G3,
            p_ghF, p_ghB, bih_f, bhh_f, bih_b, bhh_b, p_hf, p_hb, p_hfs, p_hbs);
    }

    // ---- mean + FC ----
    k_colmean<<<2 * GH, 256>>>(p_hf, p_hb, p_mean);
    k_fc<<<33, 128>>>(fc_w, fc_b, p_mean, out);
}

// round 8
// speedup vs baseline: 2.3798x; 1.0838x over previous
#include <cuda_runtime.h>
#include <cuda_bf16.h>
#include <cstdint>

#define NN     10000
#define EE     160000
#define ENTOT  (EE + NN)
#define TT     32
#define INC    128
#define HIDC   64
#define NHEADS 8
#define F1     512        // NHEADS * HID
#define GH     256
#define G3     768        // 3 * GH

// -------- phase-overlapped arenas (disjoint lifetimes; <2GB each) -----------
// ArenaA: xlr1 (GAT phase, fp32 [T*N,1024])  then  giF (GRU phase)
// ArenaB: h1s  (GAT phase, bf16 planes)      then  giB (GRU phase)
// ArenaC: xs   (input planes, pre-GEMM1)     then  embs | xlr2
#define ARENA_A_BYTES ((size_t)TT * NN * 2 * F1 * 4)            // 1,310,720,000
#define ARENA_B_BYTES ((size_t)TT * NN * G3 * 4)                //   983,040,000
#define ARENA_C_BYTES ((size_t)(2 * TT * NN * INC) * 2)         //   163,840,000 -> need 245,760,000
#define ARENA_C_REAL  ((size_t)245760000)
__device__ __align__(256) char g_arenaA[ARENA_A_BYTES];
__device__ __align__(256) char g_arenaB[ARENA_B_BYTES];
__device__ __align__(256) char g_arenaC[ARENA_C_REAL];

// ---------------- small persistent scratch ----------------
__device__ float g_degf[NN];
__device__ float g_loopsum[NN * 3];
__device__ int   g_cnt[NN];
__device__ int   g_rowptr[NN + 1];
__device__ int   g_fill[NN];
__device__ int   g_adj_src[ENTOT];
__device__ float g_adj_ea[ENTOT * 3];
__device__ float g_ghF[NN * G3];
__device__ float g_ghB[NN * G3];
__device__ float g_hf[NN * GH];
__device__ float g_hb[NN * GH];
__device__ float g_mean[2 * GH];
__device__ __nv_bfloat16 g_w1s [2 * 2 * F1 * INC];
__device__ __nv_bfloat16 g_w2s [2 * 2 * HIDC * F1];
__device__ __nv_bfloat16 g_hfs [2 * NN * GH];
__device__ __nv_bfloat16 g_hbs [2 * NN * GH];
__device__ __nv_bfloat16 g_wihs_f[2 * G3 * HIDC];
__device__ __nv_bfloat16 g_wihs_b[2 * G3 * HIDC];
__device__ __nv_bfloat16 g_whhs_f[2 * G3 * GH];
__device__ __nv_bfloat16 g_whhs_b[2 * G3 * GH];

// ---------------- helpers ----------------
#define SWZ(off) ((off) ^ (((off) >> 3) & 0x70))

__device__ __forceinline__ uint32_t smem_u32(const void* p) {
    uint32_t a;
    asm("{ .reg .u64 t; cvta.to.shared.u64 t, %1; cvt.u32.u64 %0, t; }" : "=r"(a) : "l"(p));
    return a;
}
__device__ __forceinline__ void cp_async16(uint32_t dst, const void* src, int sz) {
    asm volatile("cp.async.ca.shared.global [%0], [%1], 16, %2;"
                 :: "r"(dst), "l"(src), "r"(sz) : "memory");
}
__device__ __forceinline__ void cp_commit() {
    asm volatile("cp.async.commit_group;" ::: "memory");
}
__device__ __forceinline__ void cp_wait2() {
    asm volatile("cp.async.wait_group 2;" ::: "memory");
}
__device__ __forceinline__ void cp_wait1() {
    asm volatile("cp.async.wait_group 1;" ::: "memory");
}
__device__ __forceinline__ void cp_wait0() {
    asm volatile("cp.async.wait_group 0;" ::: "memory");
}
__device__ __forceinline__ void ldsm_x4(uint32_t* r, uint32_t addr) {
    asm volatile("ldmatrix.sync.aligned.m8n8.x4.shared.b16 {%0,%1,%2,%3}, [%4];"
                 : "=r"(r[0]), "=r"(r[1]), "=r"(r[2]), "=r"(r[3]) : "r"(addr));
}
__device__ __forceinline__ void mma_bf16(float* c, const uint32_t* a, uint32_t b0, uint32_t b1) {
    asm volatile("mma.sync.aligned.m16n8k16.row.col.f32.bf16.bf16.f32 "
                 "{%0,%1,%2,%3}, {%4,%5,%6,%7}, {%8,%9}, {%0,%1,%2,%3};"
                 : "+f"(c[0]), "+f"(c[1]), "+f"(c[2]), "+f"(c[3])
                 : "r"(a[0]), "r"(a[1]), "r"(a[2]), "r"(a[3]), "r"(b0), "r"(b1));
}
__device__ __forceinline__ void split_bf16(float v, __nv_bfloat16& hi, __nv_bfloat16& lo) {
    hi = __float2bfloat16_rn(v);
    lo = __float2bfloat16_rn(v - __bfloat162float(hi));
}

// ---- bf16x3 emulated-fp32 GEMM body: C[M,N] = A[M,K] @ BT[N,K]^T ------------
// A, B pre-split bf16 hi/lo planes ([M,K] bf16 each). BM=128, BN=128, BK=32.
// smem row (128B) = [hi 64B | lo 64B], SW128. 3-stage cp.async pipeline.
// 8 warps (2Mx4N), warp tile 64x32. K%32==0, N%128==0.
__device__ __forceinline__ void gemm_body(
    const __nv_bfloat16* __restrict__ Ahi, const __nv_bfloat16* __restrict__ Alo,
    const __nv_bfloat16* __restrict__ Bhi, const __nv_bfloat16* __restrict__ Blo,
    float* __restrict__ C, int M, int N, int K, char* smem)
{
    constexpr int TSZ   = 128 * 128;
    constexpr int STAGE = 2 * TSZ;
    const uint32_t sbase = smem_u32(smem);
    const int t = threadIdx.x;
    const int warp = t >> 5, lane = t & 31;
    const int tI = lane >> 3, lr = lane & 7;
    const int wm0 = (warp & 1) * 64;
    const int wn0 = (warp >> 1) * 32;
    const int bm = blockIdx.y * 128;
    const int bn = blockIdx.x * 128;
    const size_t Kb = (size_t)K * 2;

    float acc[4][4][4];
    #pragma unroll
    for (int i = 0; i < 4; i++)
        #pragma unroll
        for (int j = 0; j < 4; j++)
            #pragma unroll
            for (int k = 0; k < 4; k++) acc[i][j][k] = 0.f;

    const int NC = K >> 5;

    auto load_stage = [&](int s, int c) {
        uint32_t sa = sbase + s * STAGE;
        uint32_t sb = sa + TSZ;
        int k0b = c << 6;
        #pragma unroll
        for (int i = 0; i < 4; i++) {
            int idx = t + i * 256;
            int row = idx >> 3, c8 = idx & 7;
            const char* base = (const char*)((c8 & 4) ? Alo : Ahi);
            const char* src = base + (size_t)(bm + row) * Kb + k0b + (c8 & 3) * 16;
            int sz = (bm + row < M) ? 16 : 0;
            cp_async16(sa + SWZ((row << 7) | (c8 << 4)), src, sz);
        }
        #pragma unroll
        for (int i = 0; i < 4; i++) {
            int idx = t + i * 256;
            int row = idx >> 3, c8 = idx & 7;
            const char* base = (const char*)((c8 & 4) ? Blo : Bhi);
            const char* src = base + (size_t)(bn + row) * Kb + k0b + (c8 & 3) * 16;
            cp_async16(sb + SWZ((row << 7) | (c8 << 4)), src, 16);
        }
        cp_commit();
    };

    load_stage(0, 0);
    if (NC > 1) load_stage(1, 1);

    for (int c = 0; c < NC; c++) {
        if (c + 2 < NC)       { load_stage((c + 2) % 3, c + 2); cp_wait2(); }
        else if (c + 2 == NC) { cp_wait1(); }
        else                  { cp_wait0(); }
        __syncthreads();

        uint32_t sa = sbase + (c % 3) * STAGE;
        uint32_t sb = sa + TSZ;
        #pragma unroll
        for (int ks = 0; ks < 2; ks++) {
            uint32_t Ah[4][4], Al[4][4], Bh[2][4], Bl[2][4];
            #pragma unroll
            for (int ma = 0; ma < 4; ma++) {
                int row = wm0 + ma * 16 + ((tI & 1) << 3) + lr;
                int kb = (ks << 5) | ((tI >> 1) << 4);
                ldsm_x4(Ah[ma], sa + SWZ((row << 7) | kb));
                ldsm_x4(Al[ma], sa + SWZ((row << 7) | (64 + kb)));
            }
            #pragma unroll
            for (int nb = 0; nb < 2; nb++) {
                int row = wn0 + nb * 16 + ((tI >> 1) << 3) + lr;
                int kb = (ks << 5) | ((tI & 1) << 4);
                ldsm_x4(Bh[nb], sb + SWZ((row << 7) | kb));
                ldsm_x4(Bl[nb], sb + SWZ((row << 7) | (64 + kb)));
            }
            #pragma unroll
            for (int ma = 0; ma < 4; ma++)
                #pragma unroll
                for (int na = 0; na < 4; na++) {
                    int nb = na >> 1, off = (na & 1) * 2;
                    mma_bf16(acc[ma][na], Ah[ma], Bl[nb][off], Bl[nb][off + 1]);
                    mma_bf16(acc[ma][na], Al[ma], Bh[nb][off], Bh[nb][off + 1]);
                    mma_bf16(acc[ma][na], Ah[ma], Bh[nb][off], Bh[nb][off + 1]);
                }
        }
        __syncthreads();
    }

    #pragma unroll
    for (int ma = 0; ma < 4; ma++) {
        int row = bm + wm0 + ma * 16 + (lane >> 2);
        #pragma unroll
        for (int na = 0; na < 4; na++) {
            int col = bn + wn0 + na * 8 + 2 * (lane & 3);
            if (row < M)
                *reinterpret_cast<float2*>(&C[(size_t)row * N + col]) =
                    make_float2(acc[ma][na][0], acc[ma][na][1]);
            if (row + 8 < M)
                *reinterpret_cast<float2*>(&C[(size_t)(row + 8) * N + col]) =
                    make_float2(acc[ma][na][2], acc[ma][na][3]);
        }
    }
}

__global__ void __launch_bounds__(256) tgemm(
    const __nv_bfloat16* __restrict__ Ahi, const __nv_bfloat16* __restrict__ Alo,
    const __nv_bfloat16* __restrict__ Bhi, const __nv_bfloat16* __restrict__ Blo,
    float* __restrict__ C, int M, int N, int K)
{
    extern __shared__ char smem[];
    gemm_body(Ahi, Alo, Bhi, Blo, C, M, N, K, smem);
}

// z-batched variant: blockIdx.z selects pointer set (fwd / bwd direction)
__global__ void __launch_bounds__(256) tgemm_b2(
    const __nv_bfloat16* Ahi0, const __nv_bfloat16* Alo0,
    const __nv_bfloat16* Bhi0, const __nv_bfloat16* Blo0, float* C0,
    const __nv_bfloat16* Ahi1, const __nv_bfloat16* Alo1,
    const __nv_bfloat16* Bhi1, const __nv_bfloat16* Blo1, float* C1,
    int M, int N, int K)
{
    extern __shared__ char smem[];
    if (blockIdx.z == 0) gemm_body(Ahi0, Alo0, Bhi0, Blo0, C0, M, N, K, smem);
    else                 gemm_body(Ahi1, Alo1, Bhi1, Blo1, C1, M, N, K, smem);
}

// ------------- transpose + split: planes[c*R+r] = split(in[r*C + c]) --------
__global__ void k_transpose_split(const float* __restrict__ in, __nv_bfloat16* __restrict__ out,
                                  int R, int Ccols, size_t plane) {
    __shared__ float tile[32][33];
    int c0 = blockIdx.x * 32, r0 = blockIdx.y * 32;
    int x = threadIdx.x, y = threadIdx.y;
    for (int j = 0; j < 32; j += 8) {
        int r = r0 + y + j, c = c0 + x;
        if (r < R && c < Ccols) tile[y + j][x] = in[(size_t)r * Ccols + c];
    }
    __syncthreads();
    for (int j = 0; j < 32; j += 8) {
        int c = c0 + y + j, r = r0 + x;
        if (c < Ccols && r < R) {
            __nv_bfloat16 hi, lo;
            split_bf16(tile[x][y + j], hi, lo);
            out[(size_t)c * R + r] = hi;
            out[plane + (size_t)c * R + r] = lo;
        }
    }
}

__global__ void k_split(const float* __restrict__ in, __nv_bfloat16* __restrict__ out, size_t n) {
    size_t i = (size_t)blockIdx.x * blockDim.x + threadIdx.x;
    if (i >= n) return;
    __nv_bfloat16 hi, lo;
    split_bf16(in[i], hi, lo);
    out[i] = hi;
    out[n + i] = lo;
}

// ---------------- utility kernels ----------------
__global__ void k_zero_f(float* p, int n) {
    int i = blockIdx.x * blockDim.x + threadIdx.x;
    if (i < n) p[i] = 0.f;
}
__global__ void k_zero_i(int* p, int n) {
    int i = blockIdx.x * blockDim.x + threadIdx.x;
    if (i < n) p[i] = 0;
}

// ---------------- CSR precompute ----------------
__global__ void k_count(const float* __restrict__ ea, const int* __restrict__ dst,
                        float* degf, float* loopsum, int* cnt) {
    int e = blockIdx.x * blockDim.x + threadIdx.x;
    if (e >= EE) return;
    int d = dst[e];
    atomicAdd(&degf[d], 1.f);
    atomicAdd(&cnt[d], 1);
    atomicAdd(&loopsum[d * 3 + 0], ea[e * 3 + 0]);
    atomicAdd(&loopsum[d * 3 + 1], ea[e * 3 + 1]);
    atomicAdd(&loopsum[d * 3 + 2], ea[e * 3 + 2]);
}

__global__ void k_scan(const int* __restrict__ cnt, int* __restrict__ rowptr) {
    __shared__ int tmp[1024];
    __shared__ int carry_s;
    int tid = threadIdx.x;
    if (tid == 0) { carry_s = 0; rowptr[0] = 0; }
    __syncthreads();
    for (int base = 0; base < NN; base += 1024) {
        int i = base + tid;
        int v = (i < NN) ? (cnt[i] + 1) : 0;
        tmp[tid] = v;
        __syncthreads();
        #pragma unroll
        for (int off = 1; off < 1024; off <<= 1) {
            int tv = (tid >= off) ? tmp[tid - off] : 0;
            __syncthreads();
            tmp[tid] += tv;
            __syncthreads();
        }
        if (i < NN) rowptr[i + 1] = carry_s + tmp[tid];
        __syncthreads();
        if (tid == 0) carry_s += tmp[1023];
        __syncthreads();
    }
}

__global__ void k_scatter_e(const float* __restrict__ ea, const int* __restrict__ src,
                            const int* __restrict__ dst, const int* __restrict__ rowptr,
                            int* fill, int* adj_src, float* adj_ea) {
    int e = blockIdx.x * blockDim.x + threadIdx.x;
    if (e >= EE) return;
    int d = dst[e];
    int pos = rowptr[d] + atomicAdd(&fill[d], 1);
    adj_src[pos] = src[e];
    adj_ea[pos * 3 + 0] = ea[e * 3 + 0];
    adj_ea[pos * 3 + 1] = ea[e * 3 + 1];
    adj_ea[pos * 3 + 2] = ea[e * 3 + 2];
}

__global__ void k_scatter_loop(const float* __restrict__ degf, const float* __restrict__ loopsum,
                               const int* __restrict__ rowptr, int* fill,
                               int* adj_src, float* adj_ea) {
    int n = blockIdx.x * blockDim.x + threadIdx.x;
    if (n >= NN) return;
    int pos = rowptr[n] + atomicAdd(&fill[n], 1);
    adj_src[pos] = n;
    float dm = fmaxf(degf[n], 1.f);
    adj_ea[pos * 3 + 0] = loopsum[n * 3 + 0] / dm;
    adj_ea[pos * 3 + 1] = loopsum[n * 3 + 1] / dm;
    adj_ea[pos * 3 + 2] = loopsum[n * 3 + 2] / dm;
}

// ---- GAT1 edge kernel: barrier-free, warp == head, all T in one launch ----
// grid (NN, TT), block 256 (8 warps = 8 heads). xlr [T*N, 1024].
__global__ void __launch_bounds__(256) gat_edge1(
    const float* __restrict__ xlr,
    const float* __restrict__ we, const float* __restrict__ att,
    const float* __restrict__ bias,
    const int* __restrict__ rowptr, const int* __restrict__ adj_src,
    const float* __restrict__ adj_ea,
    __nv_bfloat16* __restrict__ outp)
{
    constexpr size_t H1PL = (size_t)TT * NN * F1;
    int n = blockIdx.x, tc = blockIdx.y;
    int warp = threadIdx.x >> 5, lane = threadIdx.x & 31;
    int c0 = warp * 64 + lane, c1 = c0 + 32;
    const float* base = xlr + (size_t)tc * NN * (2 * F1);
    const float* xrrow = base + (size_t)n * (2 * F1) + F1;
    float xr0 = xrrow[c0], xr1 = xrrow[c1];
    float a0 = att[c0], a1 = att[c1];
    float w00 = we[c0], w01 = we[F1 + c0], w02 = we[2 * F1 + c0];
    float w10 = we[c1], w11 = we[F1 + c1], w12 = we[2 * F1 + c1];
    int beg = rowptr[n], end = rowptr[n + 1];
    float m_run = -1e30f, s_run = 0.f, acc0 = 0.f, acc1 = 0.f;

    int src_n = adj_src[beg];
    float e0n = adj_ea[3 * beg], e1n = adj_ea[3 * beg + 1], e2n = adj_ea[3 * beg + 2];
    const float* rp = base + (size_t)src_n * (2 * F1);
    float x0n = rp[c0], x1n = rp[c1];

    for (int p = beg; p < end; p++) {
        float x0 = x0n, x1 = x1n, e0 = e0n, e1 = e1n, e2 = e2n;
        if (p + 1 < end) {
            int s2 = adj_src[p + 1];
            e0n = adj_ea[3 * (p + 1)]; e1n = adj_ea[3 * (p + 1) + 1]; e2n = adj_ea[3 * (p + 1) + 2];
            const float* rp2 = base + (size_t)s2 * (2 * F1);
            x0n = rp2[c0]; x1n = rp2[c1];
        }
        float m0 = x0 + xr0 + e0 * w00 + e1 * w01 + e2 * w02;
        float m1 = x1 + xr1 + e0 * w10 + e1 * w11 + e2 * w12;
        m0 = (m0 > 0.f) ? m0 : 0.2f * m0;
        m1 = (m1 > 0.f) ? m1 : 0.2f * m1;
        float part = m0 * a0 + m1 * a1;
        #pragma unroll
        for (int o = 16; o; o >>= 1) part += __shfl_xor_sync(0xffffffffu, part, o);
        float newm = fmaxf(m_run, part);
        float sc = __expf(m_run - newm), w = __expf(part - newm);
        s_run = s_run * sc + w;
        acc0 = acc0 * sc + w * x0;
        acc1 = acc1 * sc + w * x1;
        m_run = newm;
    }
    float inv = 1.f / s_run;
    float o0 = acc0 * inv + bias[c0];
    float o1 = acc1 * inv + bias[c1];
    o0 = (o0 > 0.f) ? o0 : (__expf(o0) - 1.f);
    o1 = (o1 > 0.f) ? o1 : (__expf(o1) - 1.f);
    size_t orow = ((size_t)tc * NN + n) * F1;
    __nv_bfloat16 hi, lo;
    split_bf16(o0, hi, lo); outp[orow + c0] = hi; outp[H1PL + orow + c0] = lo;
    split_bf16(o1, hi, lo); outp[orow + c1] = hi; outp[H1PL + orow + c1] = lo;
}

// ---- GAT2 edge kernel: warp == node (1 head), all T in one launch ---------
// grid (NN/8, TT), block 256 (8 warps = 8 nodes). xlr [T*N, 128].
__global__ void __launch_bounds__(256) gat_edge2(
    const float* __restrict__ xlr,
    const float* __restrict__ we, const float* __restrict__ att,
    const float* __restrict__ bias,
    const int* __restrict__ rowptr, const int* __restrict__ adj_src,
    const float* __restrict__ adj_ea,
    __nv_bfloat16* __restrict__ outp)
{
    constexpr size_t EMBPL = (size_t)TT * NN * HIDC;
    int warp = threadIdx.x >> 5, lane = threadIdx.x & 31;
    int n = blockIdx.x * 8 + warp, tc = blockIdx.y;
    int c0 = lane, c1 = lane + 32;
    const float* base = xlr + (size_t)tc * NN * (2 * HIDC);
    const float* xrrow = base + (size_t)n * (2 * HIDC) + HIDC;
    float xr0 = xrrow[c0], xr1 = xrrow[c1];
    float a0 = att[c0], a1 = att[c1];
    float w00 = we[c0], w01 = we[HIDC + c0], w02 = we[2 * HIDC + c0];
    float w10 = we[c1], w11 = we[HIDC + c1], w12 = we[2 * HIDC + c1];
    int beg = rowptr[n], end = rowptr[n + 1];
    float m_run = -1e30f, s_run = 0.f, acc0 = 0.f, acc1 = 0.f;

    int src_n = adj_src[beg];
    float e0n = adj_ea[3 * beg], e1n = adj_ea[3 * beg + 1], e2n = adj_ea[3 * beg + 2];
    const float* rp = base + (size_t)src_n * (2 * HIDC);
    float x0n = rp[c0], x1n = rp[c1];

    for (int p = beg; p < end; p++) {
        float x0 = x0n, x1 = x1n, e0 = e0n, e1 = e1n, e2 = e2n;
        if (p + 1 < end) {
            int s2 = adj_src[p + 1];
            e0n = adj_ea[3 * (p + 1)]; e1n = adj_ea[3 * (p + 1) + 1]; e2n = adj_ea[3 * (p + 1) + 2];
            const float* rp2 = base + (size_t)s2 * (2 * HIDC);
            x0n = rp2[c0]; x1n = rp2[c1];
        }
        float m0 = x0 + xr0 + e0 * w00 + e1 * w01 + e2 * w02;
        float m1 = x1 + xr1 + e0 * w10 + e1 * w11 + e2 * w12;
        m0 = (m0 > 0.f) ? m0 : 0.2f * m0;
        m1 = (m1 > 0.f) ? m1 : 0.2f * m1;
        float part = m0 * a0 + m1 * a1;
        #pragma unroll
        for (int o = 16; o; o >>= 1) part += __shfl_xor_sync(0xffffffffu, part, o);
        float newm = fmaxf(m_run, part);
        float sc = __expf(m_run - newm), w = __expf(part - newm);
        s_run = s_run * sc + w;
        acc0 = acc0 * sc + w * x0;
        acc1 = acc1 * sc + w * x1;
        m_run = newm;
    }
    float inv = 1.f / s_run;
    float o0 = acc0 * inv + bias[c0];
    float o1 = acc1 * inv + bias[c1];
    o0 = (o0 > 0.f) ? o0 : (__expf(o0) - 1.f);
    o1 = (o1 > 0.f) ? o1 : (__expf(o1) - 1.f);
    size_t orow = ((size_t)tc * NN + n) * HIDC;
    __nv_bfloat16 hi, lo;
    split_bf16(o0, hi, lo); outp[orow + c0] = hi; outp[EMBPL + orow + c0] = lo;
    split_bf16(o1, hi, lo); outp[orow + c1] = hi; outp[EMBPL + orow + c1] = lo;
}

// ------- GRU gate kernel, both directions, float4-vectorized ---------------
__global__ void gru_gate2(const float* __restrict__ giF, const float* __restrict__ giB,
                          const float* __restrict__ ghF, const float* __restrict__ ghB,
                          const float* __restrict__ bihf, const float* __restrict__ bhhf,
                          const float* __restrict__ bihb, const float* __restrict__ bhhb,
                          float* __restrict__ hF, float* __restrict__ hB,
                          __nv_bfloat16* __restrict__ hFs, __nv_bfloat16* __restrict__ hBs) {
    int dir = blockIdx.y;
    const float* gi  = dir ? giB : giF;
    const float* gh  = dir ? ghB : ghF;
    const float* bih = dir ? bihb : bihf;
    const float* bhh = dir ? bhhb : bhhf;
    float* h = dir ? hB : hF;
    __nv_bfloat16* hp = dir ? hBs : hFs;
    int q = blockIdx.x * blockDim.x + threadIdx.x;     // quad index
    if (q >= NN * GH / 4) return;
    int n = q / (GH / 4), j = (q % (GH / 4)) * 4;
    const float* gin = gi + (size_t)n * G3;
    const float* ghn = gh + (size_t)n * G3;
    float4 gr = *(const float4*)(gin + j);
    float4 gz = *(const float4*)(gin + GH + j);
    float4 gn = *(const float4*)(gin + 2 * GH + j);
    float4 hr = *(const float4*)(ghn + j);
    float4 hz = *(const float4*)(ghn + GH + j);
    float4 hn4 = *(const float4*)(ghn + 2 * GH + j);
    float4 br = *(const float4*)(bih + j);
    float4 bz = *(const float4*)(bih + GH + j);
    float4 bn = *(const float4*)(bih + 2 * GH + j);
    float4 cr = *(const float4*)(bhh + j);
    float4 cz = *(const float4*)(bhh + GH + j);
    float4 cn = *(const float4*)(bhh + 2 * GH + j);
    size_t hidx = (size_t)n * GH + j;
    float4 hv = *(const float4*)(h + hidx);
    float4 ho;
    #pragma unroll
    for (int k = 0; k < 4; k++) {
        float grk = (&gr.x)[k] + (&br.x)[k], hrk = (&hr.x)[k] + (&cr.x)[k];
        float gzk = (&gz.x)[k] + (&bz.x)[k], hzk = (&hz.x)[k] + (&cz.x)[k];
        float gnk = (&gn.x)[k] + (&bn.x)[k], hnk = (&hn4.x)[k] + (&cn.x)[k];
        float r = 1.f / (1.f + __expf(-(grk + hrk)));
        float z = 1.f / (1.f + __expf(-(gzk + hzk)));
        float nv = tanhf(gnk + r * hnk);
        (&ho.x)[k] = (1.f - z) * nv + z * (&hv.x)[k];
    }
    *(float4*)(h + hidx) = ho;
    #pragma unroll
    for (int k = 0; k < 4; k++) {
        __nv_bfloat16 hi, lo;
        split_bf16((&ho.x)[k], hi, lo);
        hp[hidx + k] = hi;
        hp[NN * GH + hidx + k] = lo;
    }
}

__global__ void k_zero_hplanes(float* h, __nv_bfloat16* hp) {
    int i = blockIdx.x * blockDim.x + threadIdx.x;
    if (i >= NN * GH) return;
    h[i] = 0.f;
    hp[i] = __float2bfloat16(0.f);
    hp[NN * GH + i] = __float2bfloat16(0.f);
}

// ---------------- final reductions ----------------
__global__ void k_colmean(const float* __restrict__ hf, const float* __restrict__ hb,
                          float* __restrict__ mean) {
    int j = blockIdx.x;
    const float* base = (j < GH) ? (hf + j) : (hb + (j - GH));
    float s = 0.f;
    for (int n = threadIdx.x; n < NN; n += blockDim.x) s += base[(size_t)n * GH];
    __shared__ float sh[256];
    sh[threadIdx.x] = s;
    __syncthreads();
    for (int o = 128; o; o >>= 1) {
        if (threadIdx.x < o) sh[threadIdx.x] += sh[threadIdx.x + o];
        __syncthreads();
    }
    if (threadIdx.x == 0) mean[j] = sh[0] * (1.f / (float)NN);
}

__global__ void k_fc(const float* __restrict__ w, const float* __restrict__ b,
                     const float* __restrict__ mean, float* __restrict__ out) {
    int i = blockIdx.x;
    float s = 0.f;
    for (int j = threadIdx.x; j < 2 * GH; j += blockDim.x) s += w[i * 2 * GH + j] * mean[j];
    __shared__ float sh[128];
    sh[threadIdx.x] = s;
    __syncthreads();
    for (int o = 64; o; o >>= 1) {
        if (threadIdx.x < o) sh[threadIdx.x] += sh[threadIdx.x + o];
        __syncthreads();
    }
    if (threadIdx.x == 0) out[i] = sh[0] + b[i];
}

// ---------------- host ----------------
static const int GEMM_SMEM = 3 * 2 * 128 * 128;   // 98304 (3 stages)

extern "C" void kernel_launch(void* const* d_in, const int* in_sizes, int n_in,
                              void* d_out, int out_size) {
    const float* x        = (const float*)d_in[0];
    const float* edge_ea  = (const float*)d_in[1];
    const int*   edge_src = (const int*)  d_in[2];
    const int*   edge_dst = (const int*)  d_in[3];
    const float* gat1_wl  = (const float*)d_in[4];
    const float* gat1_wr  = (const float*)d_in[5];
    const float* gat1_we  = (const float*)d_in[6];
    const float* gat1_att = (const float*)d_in[7];
    const float* gat1_b   = (const float*)d_in[8];
    const float* gat2_wl  = (const float*)d_in[9];
    const float* gat2_wr  = (const float*)d_in[10];
    const float* gat2_we  = (const float*)d_in[11];
    const float* gat2_att = (const float*)d_in[12];
    const float* gat2_b   = (const float*)d_in[13];
    const float* wih_f    = (const float*)d_in[14];
    const float* whh_f    = (const float*)d_in[15];
    const float* bih_f    = (const float*)d_in[16];
    const float* bhh_f    = (const float*)d_in[17];
    const float* wih_b    = (const float*)d_in[18];
    const float* whh_b    = (const float*)d_in[19];
    const float* bih_b    = (const float*)d_in[20];
    const float* bhh_b    = (const float*)d_in[21];
    const float* fc_w     = (const float*)d_in[22];
    const float* fc_b     = (const float*)d_in[23];
    float* out = (float*)d_out;

    cudaFuncSetAttribute(tgemm, cudaFuncAttributeMaxDynamicSharedMemorySize, GEMM_SMEM);
    cudaFuncSetAttribute(tgemm_b2, cudaFuncAttributeMaxDynamicSharedMemorySize, GEMM_SMEM);

    float *p_degf, *p_loopsum, *p_adj_ea, *p_ghF, *p_ghB, *p_hf, *p_hb, *p_mean;
    int *p_cnt, *p_rowptr, *p_fill, *p_adj_src;
    __nv_bfloat16 *p_w1s, *p_w2s, *p_hfs, *p_hbs;
    __nv_bfloat16 *p_wihs_f, *p_wihs_b, *p_whhs_f, *p_whhs_b;
    char *arA, *arB, *arC;
    cudaGetSymbolAddress((void**)&p_degf, g_degf);
    cudaGetSymbolAddress((void**)&p_loopsum, g_loopsum);
    cudaGetSymbolAddress((void**)&p_cnt, g_cnt);
    cudaGetSymbolAddress((void**)&p_rowptr, g_rowptr);
    cudaGetSymbolAddress((void**)&p_fill, g_fill);
    cudaGetSymbolAddress((void**)&p_adj_src, g_adj_src);
    cudaGetSymbolAddress((void**)&p_adj_ea, g_adj_ea);
    cudaGetSymbolAddress((void**)&p_ghF, g_ghF);
    cudaGetSymbolAddress((void**)&p_ghB, g_ghB);
    cudaGetSymbolAddress((void**)&p_hf,  g_hf);
    cudaGetSymbolAddress((void**)&p_hb,  g_hb);
    cudaGetSymbolAddress((void**)&p_mean, g_mean);
    cudaGetSymbolAddress((void**)&p_w1s, g_w1s);
    cudaGetSymbolAddress((void**)&p_w2s, g_w2s);
    cudaGetSymbolAddress((void**)&p_hfs, g_hfs);
    cudaGetSymbolAddress((void**)&p_hbs, g_hbs);
    cudaGetSymbolAddress((void**)&p_wihs_f, g_wihs_f);
    cudaGetSymbolAddress((void**)&p_wihs_b, g_wihs_b);
    cudaGetSymbolAddress((void**)&p_whhs_f, g_whhs_f);
    cudaGetSymbolAddress((void**)&p_whhs_b, g_whhs_b);
    cudaGetSymbolAddress((void**)&arA, g_arenaA);
    cudaGetSymbolAddress((void**)&arB, g_arenaB);
    cudaGetSymbolAddress((void**)&arC, g_arenaC);

    // arena-carved pointers (phase-disjoint lifetimes)
    float*         p_xlr1 = (float*)arA;                    // GAT: [T*N, 1024]
    float*         p_giF  = (float*)arA;                    // GRU: [T*N, G3]
    __nv_bfloat16* p_h1s  = (__nv_bfloat16*)arB;            // GAT: planes
    float*         p_giB  = (float*)arB;                    // GRU: [T*N, G3]
    __nv_bfloat16* p_xs   = (__nv_bfloat16*)arC;            // pre-GEMM1 planes
    __nv_bfloat16* p_embs = (__nv_bfloat16*)arC;            // post-edge2 planes
    float*         p_xlr2 = (float*)(arC + 81920000);       // GAT: [T*N, 128]

    const int TB = 256;
    // ---- CSR precompute ----
    k_zero_f<<<(NN + TB - 1) / TB, TB>>>(p_degf, NN);
    k_zero_f<<<(3 * NN + TB - 1) / TB, TB>>>(p_loopsum, 3 * NN);
    k_zero_i<<<(NN + TB - 1) / TB, TB>>>(p_cnt, NN);
    k_count<<<(EE + TB - 1) / TB, TB>>>(edge_ea, edge_dst, p_degf, p_loopsum, p_cnt);
    k_scan<<<1, 1024>>>(p_cnt, p_rowptr);
    k_zero_i<<<(NN + TB - 1) / TB, TB>>>(p_fill, NN);
    k_scatter_e<<<(EE + TB - 1) / TB, TB>>>(edge_ea, edge_src, edge_dst, p_rowptr,
                                            p_fill, p_adj_src, p_adj_ea);
    k_scatter_loop<<<(NN + TB - 1) / TB, TB>>>(p_degf, p_loopsum, p_rowptr,
                                               p_fill, p_adj_src, p_adj_ea);

    // ---- weight transposes + splits into bf16 planes ----
    {
        dim3 b(32, 8);
        size_t pl1 = (size_t)2 * F1 * INC;
        k_transpose_split<<<dim3(F1 / 32, INC / 32), b>>>(gat1_wl, p_w1s, INC, F1, pl1);
        k_transpose_split<<<dim3(F1 / 32, INC / 32), b>>>(gat1_wr, p_w1s + (size_t)F1 * INC, INC, F1, pl1);
        size_t pl2 = (size_t)2 * HIDC * F1;
        k_transpose_split<<<dim3(HIDC / 32, F1 / 32), b>>>(gat2_wl, p_w2s, F1, HIDC, pl2);
        k_transpose_split<<<dim3(HIDC / 32, F1 / 32), b>>>(gat2_wr, p_w2s + (size_t)HIDC * F1, F1, HIDC, pl2);
    }
    k_split<<<(G3 * HIDC + TB - 1) / TB, TB>>>(wih_f, p_wihs_f, (size_t)G3 * HIDC);
    k_split<<<(G3 * HIDC + TB - 1) / TB, TB>>>(wih_b, p_wihs_b, (size_t)G3 * HIDC);
    k_split<<<(G3 * GH + TB - 1) / TB, TB>>>(whh_f, p_whhs_f, (size_t)G3 * GH);
    k_split<<<(G3 * GH + TB - 1) / TB, TB>>>(whh_b, p_whhs_b, (size_t)G3 * GH);
    {
        size_t nx = (size_t)TT * NN * INC;
        k_split<<<(int)((nx + TB - 1) / TB), TB>>>(x, p_xs, nx);
    }

    const size_t XPL   = (size_t)TT * NN * INC;
    const size_t H1PL  = (size_t)TT * NN * F1;
    const size_t EMBPL = (size_t)TT * NN * HIDC;
    const size_t W1PL  = (size_t)2 * F1 * INC;
    const size_t W2PL  = (size_t)2 * HIDC * F1;
    const size_t WIHPL = (size_t)G3 * HIDC;
    const size_t WHHPL = (size_t)G3 * GH;

    // ---- GAT phase: all 32 timesteps in one pass (4 launches) ----
    tgemm<<<dim3((2 * F1) / 128, (TT * NN + 127) / 128), 256, GEMM_SMEM>>>(
        p_xs, p_xs + XPL, p_w1s, p_w1s + W1PL, p_xlr1, TT * NN, 2 * F1, INC);
    gat_edge1<<<dim3(NN, TT), 256>>>(p_xlr1, gat1_we, gat1_att, gat1_b,
                                     p_rowptr, p_adj_src, p_adj_ea, p_h1s);
    tgemm<<<dim3(1, (TT * NN + 127) / 128), 256, GEMM_SMEM>>>(
        p_h1s, p_h1s + H1PL, p_w2s, p_w2s + W2PL, p_xlr2, TT * NN, 2 * HIDC, F1);
    gat_edge2<<<dim3(NN / 8, TT), 256>>>(p_xlr2, gat2_we, gat2_att, gat2_b,
                                         p_rowptr, p_adj_src, p_adj_ea, p_embs);

    // ---- batched gi GEMMs (both directions, all T) ----
    tgemm_b2<<<dim3(G3 / 128, (TT * NN + 127) / 128, 2), 256, GEMM_SMEM>>>(
        p_embs, p_embs + EMBPL, p_wihs_f, p_wihs_f + WIHPL, p_giF,
        p_embs, p_embs + EMBPL, p_wihs_b, p_wihs_b + WIHPL, p_giB,
        TT * NN, G3, HIDC);

    // ---- GRU chain: fwd + bwd batched per step ----
    k_zero_hplanes<<<(NN * GH + TB - 1) / TB, TB>>>(p_hf, p_hfs);
    k_zero_hplanes<<<(NN * GH + TB - 1) / TB, TB>>>(p_hb, p_hbs);
    for (int t = 0; t < TT; t++) {
        tgemm_b2<<<dim3(G3 / 128, (NN + 127) / 128, 2), 256, GEMM_SMEM>>>(
            p_hfs, p_hfs + NN * GH, p_whhs_f, p_whhs_f + WHHPL, p_ghF,
            p_hbs, p_hbs + NN * GH, p_whhs_b, p_whhs_b + WHHPL, p_ghB,
            NN, G3, GH);
        gru_gate2<<<dim3((NN * GH / 4 + TB - 1) / TB, 2), TB>>>(
            p_giF + (size_t)t * NN * G3, p_giB + (size_t)(TT - 1 - t) * NN * G3,
            p_ghF, p_ghB, bih_f, bhh_f, bih_b, bhh_b, p_hf, p_hb, p_hfs, p_hbs);
    }

    // ---- mean + FC ----
    k_colmean<<<2 * GH, 256>>>(p_hf, p_hb, p_mean);
    k_fc<<<33, 128>>>(fc_w, fc_b, p_mean, out);
}